// round 4
// baseline (speedup 1.0000x reference)
#include <cuda_runtime.h>

#define NNODES_MAX 50000
#define HF 128

// Scratch: U[n][j] = b1[j] + sum_k W1[j][k]*h[n][k],  V[n][j] = sum_k W1[j][128+k]*h[n][k]
__device__ float g_U[NNODES_MAX * HF];
__device__ float g_V[NNODES_MAX * HF];

// ---------------------------------------------------------------------------
// Kernel 1: node GEMM  C[n][c] = sum_k h[n][k] * Wc[k][c]   (M=n_nodes, N=256, K=128)
//   Wc[k][c] = W1[c & 127][ ((c>>7)<<7) + k ]
// CTA tile 64 nodes x 256 cols, K chunked by 32.
// Thread tile: 8 rows (8*ty..8*ty+7) x 8 cols (U[4tx..4tx+4) and V[4tx..4tx+4)).
// A is stored pair-duplicated in smem so both A {a,a} and B {b0,b1} f32x2
// operands come straight out of LDS.128 — zero packing movs in the inner loop.
// ---------------------------------------------------------------------------
__global__ __launch_bounds__(256, 2) void node_gemm_kernel(
    const float* __restrict__ h,
    const float* __restrict__ W1,
    const float* __restrict__ b1,
    int n_nodes)
{
    __shared__ float Hs2[32][132];   // [k][2r]=[k][2r+1]=h[r][k]; 16.9 KB
    __shared__ float Ws[32][260];    // [k][c]; 33.3 KB; rows 16B-aligned

    const int tid = threadIdx.x;
    const int tx  = tid & 31;        // col group: cols 4tx..4tx+3 (U and V halves)
    const int ty  = tid >> 5;        // row group: rows 8ty..8ty+7
    const int n0  = blockIdx.x * 64;

    unsigned long long acc2[8][4];   // [row r][pair j]: j=0,1 U cols, j=2,3 V cols
#pragma unroll
    for (int r = 0; r < 8; r++)
#pragma unroll
        for (int j = 0; j < 4; j++) acc2[r][j] = 0ull;

    for (int kc = 0; kc < 4; kc++) {
        __syncthreads();
        // H chunk -> Hs2 duplicated: 64 rows x 32 k
#pragma unroll
        for (int e = tid; e < 64 * 8; e += 256) {
            int r  = e >> 3;
            int c4 = e & 7;
            int n  = n0 + r;
            float4 v = make_float4(0.f, 0.f, 0.f, 0.f);
            if (n < n_nodes)
                v = *(const float4*)(h + (size_t)n * HF + kc * 32 + c4 * 4);
            *(float2*)&Hs2[c4 * 4 + 0][2 * r] = make_float2(v.x, v.x);
            *(float2*)&Hs2[c4 * 4 + 1][2 * r] = make_float2(v.y, v.y);
            *(float2*)&Hs2[c4 * 4 + 2][2 * r] = make_float2(v.z, v.z);
            *(float2*)&Hs2[c4 * 4 + 3][2 * r] = make_float2(v.w, v.w);
        }
        // W chunk: Ws[k][c], c in [0,256)
#pragma unroll
        for (int e = tid; e < 2048; e += 256) {
            int c   = e >> 3;                 // 0..255
            int k0  = (e & 7) * 4;            // 0,4,...,28
            int row = c & 127;
            int gk  = ((c >> 7) << 7) + kc * 32 + k0;
            float4 w = *(const float4*)(W1 + row * 256 + gk);
            Ws[k0 + 0][c] = w.x;
            Ws[k0 + 1][c] = w.y;
            Ws[k0 + 2][c] = w.z;
            Ws[k0 + 3][c] = w.w;
        }
        __syncthreads();

#pragma unroll 8
        for (int k = 0; k < 32; k++) {
            // A: 4 broadcast LDS.128; each half is {h_r, h_r} packed
            unsigned long long a2[8];
#pragma unroll
            for (int p = 0; p < 4; p++) {
                ulonglong2 av = *(const ulonglong2*)(&Hs2[k][16 * ty + 4 * p]);
                a2[2 * p + 0] = av.x;   // row 8ty+2p
                a2[2 * p + 1] = av.y;   // row 8ty+2p+1
            }
            // B: 2 LDS.128, conflict-free (512B contiguous across warp)
            ulonglong2 bu = *(const ulonglong2*)(&Ws[k][4 * tx]);        // U cols
            ulonglong2 bv = *(const ulonglong2*)(&Ws[k][128 + 4 * tx]);  // V cols
            unsigned long long b2[4] = { bu.x, bu.y, bv.x, bv.y };

#pragma unroll
            for (int r = 0; r < 8; r++)
#pragma unroll
                for (int j = 0; j < 4; j++)
                    asm("fma.rn.f32x2 %0, %1, %2, %0;"
                        : "+l"(acc2[r][j]) : "l"(a2[r]), "l"(b2[j]));
        }
    }

    // Epilogue: fold b1 into U; coalesced float4 stores.
    const float4 b1v = *(const float4*)(b1 + 4 * tx);
#pragma unroll
    for (int r = 0; r < 8; r++) {
        int n = n0 + 8 * ty + r;
        if (n < n_nodes) {
            float2 u0 = *(float2*)&acc2[r][0];
            float2 u1 = *(float2*)&acc2[r][1];
            float2 v0 = *(float2*)&acc2[r][2];
            float2 v1 = *(float2*)&acc2[r][3];
            float4 uo = make_float4(u0.x + b1v.x, u0.y + b1v.y,
                                    u1.x + b1v.z, u1.y + b1v.w);
            float4 vo = make_float4(v0.x, v0.y, v1.x, v1.y);
            *(float4*)(g_U + (size_t)n * HF + 4 * tx) = uo;
            *(float4*)(g_V + (size_t)n * HF + 4 * tx) = vo;
        }
    }
}

// ---------------------------------------------------------------------------
// Kernel 2: per-edge  score = W2 . relu(U'[src] + V[dst]) + b2   (b1 in U')
// 4 edges per warp, 8 lanes per edge; 3-level xor reduction shared by 4 edges.
// ---------------------------------------------------------------------------
__global__ __launch_bounds__(256) void edge_score_kernel(
    const void* __restrict__ src_raw,
    const void* __restrict__ dst_raw,
    const float* __restrict__ W2,
    const float* __restrict__ b2,
    float* __restrict__ out,
    int n_edges,
    int n_nodes)
{
    __shared__ int s_is64;
    if (threadIdx.x == 0) {
        // If genuinely int64 (indices < 50000), every high word is 0.
        const unsigned int* p = (const unsigned int*)src_raw;
        int slots = n_edges >> 1; if (slots > 64) slots = 64;
        unsigned int acc = 0;
        for (int i = 0; i < slots; i++) acc |= p[2 * i + 1];
        s_is64 = (acc == 0u) ? 1 : 0;
    }
    __syncthreads();
    const int is64 = s_is64;

    const int lane = threadIdx.x & 31;
    const int q    = lane >> 3;              // edge slot within warp (0..3)
    const int t    = lane & 7;               // sub-lane within edge (0..7)
    const int warp   = (blockIdx.x * blockDim.x + threadIdx.x) >> 5;
    const int nwarps = (gridDim.x * blockDim.x) >> 5;

    // Lane's 16 W2 coefficients: float4s at indices t + 8m (floats 4t+32m..+4)
    float4 w2r[4];
#pragma unroll
    for (int m = 0; m < 4; m++)
        w2r[m] = ((const float4*)W2)[t + 8 * m];
    const float b2v = __ldg(b2);

    const int*       src32 = (const int*)src_raw;
    const int*       dst32 = (const int*)dst_raw;
    const long long* src64 = (const long long*)src_raw;
    const long long* dst64 = (const long long*)dst_raw;

    const int n_iter = (n_edges + 3) >> 2;
    for (int it = warp; it < n_iter; it += nwarps) {
        const int e = it * 4 + q;
        const bool live = (e < n_edges);

        int s = 0, d = 0;
        if (live) {
            if (is64) {
                s = (int)__ldg(src64 + e);
                d = (int)__ldg(dst64 + e);
            } else {
                s = __ldg(src32 + e);
                d = __ldg(dst32 + e);
            }
        }
        // Safety clamp: bad index -> wrong value at worst, never a fault.
        unsigned int su = ((unsigned int)s < (unsigned int)n_nodes) ? (unsigned int)s : 0u;
        unsigned int du = ((unsigned int)d < (unsigned int)n_nodes) ? (unsigned int)d : 0u;

        const float4* urow = (const float4*)(g_U + (size_t)su * HF);
        const float4* vrow = (const float4*)(g_V + (size_t)du * HF);

        float acc = 0.f;
#pragma unroll
        for (int m = 0; m < 4; m++) {
            float4 u = urow[t + 8 * m];      // group covers one 128B line / instr
            float4 v = vrow[t + 8 * m];
            acc = fmaf(fmaxf(u.x + v.x, 0.f), w2r[m].x, acc);
            acc = fmaf(fmaxf(u.y + v.y, 0.f), w2r[m].y, acc);
            acc = fmaf(fmaxf(u.z + v.z, 0.f), w2r[m].z, acc);
            acc = fmaf(fmaxf(u.w + v.w, 0.f), w2r[m].w, acc);
        }

        // Reduce over the 8 sub-lanes (offsets stay inside the 8-lane group)
        acc += __shfl_xor_sync(0xffffffffu, acc, 1);
        acc += __shfl_xor_sync(0xffffffffu, acc, 2);
        acc += __shfl_xor_sync(0xffffffffu, acc, 4);

        if (t == 0 && live) out[e] = acc + b2v;   // 4 lanes -> 16B coalesced
    }
}

// ---------------------------------------------------------------------------
// Launch
// ---------------------------------------------------------------------------
extern "C" void kernel_launch(void* const* d_in, const int* in_sizes, int n_in,
                              void* d_out, int out_size)
{
    const float* h   = (const float*)d_in[0];
    const void*  src = d_in[1];
    const void*  dst = d_in[2];
    const float* W1  = (const float*)d_in[3];
    const float* b1  = (const float*)d_in[4];
    const float* W2  = (const float*)d_in[5];
    const float* b2  = (const float*)d_in[6];
    float* out = (float*)d_out;

    const int n_nodes = in_sizes[0] / HF;
    const int n_edges = in_sizes[1];

    node_gemm_kernel<<<(n_nodes + 63) / 64, 256>>>(h, W1, b1, n_nodes);
    edge_score_kernel<<<1184, 256>>>(src, dst, W2, b2, out, n_edges, n_nodes);
}

// round 6
// speedup vs baseline: 1.0634x; 1.0634x over previous
#include <cuda_runtime.h>
#include <cstdint>

#define NNODES_MAX 50000
#define HF 128

// U[n][j] = b1[j] + sum_k W1[j][k]*h[n][k],  V[n][j] = sum_k W1[j][128+k]*h[n][k]
__device__ float g_U[NNODES_MAX * HF];
__device__ float g_V[NNODES_MAX * HF];

// ---------------------------------------------------------------------------
// Kernel 1: node GEMM  C[n][c] = sum_k h[n][k] * Wc[k][c]   (M=n_nodes, N=256, K=128)
//   Wc[k][c] = W1[c & 127][ ((c>>7)<<7) + k ]
// CTA tile 128 nodes x 256 cols, K chunked by 32. 256 threads.
// Thread tile: 16 rows (8 f32x2 row-PAIRS) x 8 cols.
//   A: HsT[k][r] transposed -> LDS.64 = {h_r, h_r+1}, warp-broadcast.
//   B: Ws2[k][2c] = {w,w} duplicated  -> LDS.64 splat, 256B/warp conflict-free.
// Zero packing movs; 64 FFMA2 per 16 LDS.64 per k -> FFMA2-pipe bound.
// ---------------------------------------------------------------------------
#define HST_LD 130   // floats per HsT row (even -> 8B aligned; 2-way fill conflicts only)
#define WS2_LD 522   // floats per Ws2 row (even; fill ~2-way)
#define GEMM_SMEM ((32 * HST_LD + 32 * WS2_LD) * 4)

__global__ __launch_bounds__(256, 1) void node_gemm_kernel(
    const float* __restrict__ h,
    const float* __restrict__ W1,
    const float* __restrict__ b1,
    int n_nodes)
{
    extern __shared__ float sm[];
    float* HsT = sm;                  // [32][HST_LD]  (k-major, transposed)
    float* Ws2 = sm + 32 * HST_LD;    // [32][WS2_LD]  (k-major, col-duplicated)

    const int tid = threadIdx.x;
    const int tx  = tid & 31;         // cols c = tx + 32j
    const int ty  = tid >> 5;         // rows 16*ty .. 16*ty+15
    const int n0  = blockIdx.x * 128;

    unsigned long long acc2[8][8];    // [row pair p][col j]
#pragma unroll
    for (int p = 0; p < 8; p++)
#pragma unroll
        for (int j = 0; j < 8; j++) acc2[p][j] = 0ull;

    for (int kc = 0; kc < 4; kc++) {
        __syncthreads();
        // ---- fill HsT (transposed): 128 nodes x 32 k ----
#pragma unroll
        for (int e = tid; e < 128 * 8; e += 256) {
            int r  = e >> 3;
            int c4 = e & 7;
            int n  = n0 + r;
            float4 v = make_float4(0.f, 0.f, 0.f, 0.f);
            if (n < n_nodes)
                v = *(const float4*)(h + (size_t)n * HF + kc * 32 + c4 * 4);
            HsT[(c4 * 4 + 0) * HST_LD + r] = v.x;
            HsT[(c4 * 4 + 1) * HST_LD + r] = v.y;
            HsT[(c4 * 4 + 2) * HST_LD + r] = v.z;
            HsT[(c4 * 4 + 3) * HST_LD + r] = v.w;
        }
        // ---- fill Ws2 (duplicated): Ws2[k][2c]=Ws2[k][2c+1]=Wc[k][c] ----
#pragma unroll
        for (int e = tid; e < 2048; e += 256) {
            int c   = e >> 3;                  // 0..255
            int k0  = (e & 7) * 4;             // 0,4,...,28
            int row = c & 127;
            int gk  = ((c >> 7) << 7) + kc * 32 + k0;
            float4 w = *(const float4*)(W1 + row * 256 + gk);
            *(float2*)&Ws2[(k0 + 0) * WS2_LD + 2 * c] = make_float2(w.x, w.x);
            *(float2*)&Ws2[(k0 + 1) * WS2_LD + 2 * c] = make_float2(w.y, w.y);
            *(float2*)&Ws2[(k0 + 2) * WS2_LD + 2 * c] = make_float2(w.z, w.z);
            *(float2*)&Ws2[(k0 + 3) * WS2_LD + 2 * c] = make_float2(w.w, w.w);
        }
        __syncthreads();

#pragma unroll 4
        for (int k = 0; k < 32; k++) {
            unsigned long long a2[8];
            const float* hrow = HsT + k * HST_LD + 16 * ty;
#pragma unroll
            for (int p = 0; p < 8; p++)
                a2[p] = *(const unsigned long long*)(hrow + 2 * p);

            const float* wrow = Ws2 + k * WS2_LD + 2 * tx;
#pragma unroll
            for (int j = 0; j < 8; j++) {
                unsigned long long b2 = *(const unsigned long long*)(wrow + 64 * j);
#pragma unroll
                for (int p = 0; p < 8; p++)
                    asm("fma.rn.f32x2 %0, %1, %2, %0;"
                        : "+l"(acc2[p][j]) : "l"(a2[p]), "l"(b2));
            }
        }
    }

    // ---- epilogue: fold b1 into U cols; coalesced scalar stores ----
    float b1r[4];
#pragma unroll
    for (int j = 0; j < 4; j++) b1r[j] = __ldg(b1 + tx + 32 * j);

#pragma unroll
    for (int p = 0; p < 8; p++) {
        int r0 = n0 + 16 * ty + 2 * p;
#pragma unroll
        for (int half = 0; half < 2; half++) {
            int n = r0 + half;
            if (n < n_nodes) {
                float* __restrict__ urow = g_U + (size_t)n * HF;
                float* __restrict__ vrow = g_V + (size_t)n * HF;
#pragma unroll
                for (int j = 0; j < 8; j++) {
                    float val = ((const float*)&acc2[p][j])[half];
                    int c = tx + 32 * j;
                    if (j < 4) urow[c]       = val + b1r[j];
                    else       vrow[c - 128] = val;
                }
            }
        }
    }
}

// ---------------------------------------------------------------------------
// Kernel 2: per-edge  score = W2 . relu(U'[src] + V[dst]) + b2   (b1 in U')
// 4 edges per warp, 8 lanes per edge; 3-level xor reduction shared by 4 edges.
// ---------------------------------------------------------------------------
__global__ __launch_bounds__(256) void edge_score_kernel(
    const void* __restrict__ src_raw,
    const void* __restrict__ dst_raw,
    const float* __restrict__ W2,
    const float* __restrict__ b2,
    float* __restrict__ out,
    int n_edges,
    int n_nodes)
{
    __shared__ int s_is64;
    if (threadIdx.x == 0) {
        // If genuinely int64 (indices < 50000), every high word is 0.
        const unsigned int* p = (const unsigned int*)src_raw;
        int slots = n_edges >> 1; if (slots > 64) slots = 64;
        unsigned int acc = 0;
        for (int i = 0; i < slots; i++) acc |= p[2 * i + 1];
        s_is64 = (acc == 0u) ? 1 : 0;
    }
    __syncthreads();
    const int is64 = s_is64;

    const int lane = threadIdx.x & 31;
    const int q    = lane >> 3;               // edge slot within warp (0..3)
    const int t    = lane & 7;                // sub-lane within edge (0..7)
    const int warp   = (blockIdx.x * blockDim.x + threadIdx.x) >> 5;
    const int nwarps = (gridDim.x * blockDim.x) >> 5;

    float4 w2r[4];
#pragma unroll
    for (int mm = 0; mm < 4; mm++)
        w2r[mm] = ((const float4*)W2)[t + 8 * mm];
    const float b2v = __ldg(b2);

    const int*       src32 = (const int*)src_raw;
    const int*       dst32 = (const int*)dst_raw;
    const long long* src64 = (const long long*)src_raw;
    const long long* dst64 = (const long long*)dst_raw;

    const int n_iter = (n_edges + 3) >> 2;
    for (int it = warp; it < n_iter; it += nwarps) {
        const int e = it * 4 + q;
        const bool live = (e < n_edges);

        int s = 0, d = 0;
        if (live) {
            if (is64) {
                s = (int)__ldg(src64 + e);
                d = (int)__ldg(dst64 + e);
            } else {
                s = __ldg(src32 + e);
                d = __ldg(dst32 + e);
            }
        }
        unsigned int su = ((unsigned int)s < (unsigned int)n_nodes) ? (unsigned int)s : 0u;
        unsigned int du = ((unsigned int)d < (unsigned int)n_nodes) ? (unsigned int)d : 0u;

        const float4* urow = (const float4*)(g_U + (size_t)su * HF);
        const float4* vrow = (const float4*)(g_V + (size_t)du * HF);

        float acc = 0.f;
#pragma unroll
        for (int mm = 0; mm < 4; mm++) {
            float4 u = urow[t + 8 * mm];
            float4 v = vrow[t + 8 * mm];
            acc = fmaf(fmaxf(u.x + v.x, 0.f), w2r[mm].x, acc);
            acc = fmaf(fmaxf(u.y + v.y, 0.f), w2r[mm].y, acc);
            acc = fmaf(fmaxf(u.z + v.z, 0.f), w2r[mm].z, acc);
            acc = fmaf(fmaxf(u.w + v.w, 0.f), w2r[mm].w, acc);
        }
        acc += __shfl_xor_sync(0xffffffffu, acc, 1);
        acc += __shfl_xor_sync(0xffffffffu, acc, 2);
        acc += __shfl_xor_sync(0xffffffffu, acc, 4);

        if (t == 0 && live) out[e] = acc + b2v;
    }
}

// ---------------------------------------------------------------------------
// Launch
// ---------------------------------------------------------------------------
extern "C" void kernel_launch(void* const* d_in, const int* in_sizes, int n_in,
                              void* d_out, int out_size)
{
    const float* h   = (const float*)d_in[0];
    const void*  src = d_in[1];
    const void*  dst = d_in[2];
    const float* W1  = (const float*)d_in[3];
    const float* b1  = (const float*)d_in[4];
    const float* W2  = (const float*)d_in[5];
    const float* b2  = (const float*)d_in[6];
    float* out = (float*)d_out;

    const int n_nodes = in_sizes[0] / HF;
    const int n_edges = in_sizes[1];
    const int n_tiles = (n_nodes + 127) / 128;

    static int smem_set = 0;
    if (!smem_set) {
        cudaFuncSetAttribute(node_gemm_kernel,
                             cudaFuncAttributeMaxDynamicSharedMemorySize, GEMM_SMEM);
        smem_set = 1;
    }
    node_gemm_kernel<<<n_tiles, 256, GEMM_SMEM>>>(h, W1, b1, n_nodes);
    edge_score_kernel<<<1184, 256>>>(src, dst, W2, b2, out, n_edges, n_nodes);
}

// round 7
// speedup vs baseline: 1.2171x; 1.1446x over previous
#include <cuda_runtime.h>
#include <cuda_fp16.h>
#include <cstdint>

#define NNODES_MAX 50000
#define HF 128

// U[n][j] = b1[j] + sum_k W1[j][k]*h[n][k],  V[n][j] = sum_k W1[j][128+k]*h[n][k]
// Stored as fp16: halves edge-phase L2 bytes; GEMM math stays fp32.
__device__ __half g_U[NNODES_MAX * HF];
__device__ __half g_V[NNODES_MAX * HF];

// ---------------------------------------------------------------------------
// Kernel 1: node GEMM  C[n][c] = sum_k h[n][k] * Wc[k][c]   (M=n_nodes, N=256, K=128)
// CTA tile 128 nodes x 256 cols, K chunked by 32. 256 threads.
// Thread tile: 16 rows (8 f32x2 row-PAIRS) x 8 cols, fma.rn.f32x2 accumulate.
// ---------------------------------------------------------------------------
#define HST_LD 130
#define WS2_LD 522
#define GEMM_SMEM ((32 * HST_LD + 32 * WS2_LD) * 4)

__global__ __launch_bounds__(256, 1) void node_gemm_kernel(
    const float* __restrict__ h,
    const float* __restrict__ W1,
    const float* __restrict__ b1,
    int n_nodes)
{
    extern __shared__ float sm[];
    float* HsT = sm;                  // [32][HST_LD]  (k-major, transposed)
    float* Ws2 = sm + 32 * HST_LD;    // [32][WS2_LD]  (k-major, col-duplicated)

    const int tid = threadIdx.x;
    const int tx  = tid & 31;         // cols c = tx + 32j
    const int ty  = tid >> 5;         // rows 16*ty .. 16*ty+15
    const int n0  = blockIdx.x * 128;

    unsigned long long acc2[8][8];    // [row pair p][col j]
#pragma unroll
    for (int p = 0; p < 8; p++)
#pragma unroll
        for (int j = 0; j < 8; j++) acc2[p][j] = 0ull;

    for (int kc = 0; kc < 4; kc++) {
        __syncthreads();
        // ---- fill HsT (transposed): 128 nodes x 32 k ----
#pragma unroll
        for (int e = tid; e < 128 * 8; e += 256) {
            int r  = e >> 3;
            int c4 = e & 7;
            int n  = n0 + r;
            float4 v = make_float4(0.f, 0.f, 0.f, 0.f);
            if (n < n_nodes)
                v = *(const float4*)(h + (size_t)n * HF + kc * 32 + c4 * 4);
            HsT[(c4 * 4 + 0) * HST_LD + r] = v.x;
            HsT[(c4 * 4 + 1) * HST_LD + r] = v.y;
            HsT[(c4 * 4 + 2) * HST_LD + r] = v.z;
            HsT[(c4 * 4 + 3) * HST_LD + r] = v.w;
        }
        // ---- fill Ws2 (duplicated): Ws2[k][2c]=Ws2[k][2c+1]=Wc[k][c] ----
#pragma unroll
        for (int e = tid; e < 2048; e += 256) {
            int c   = e >> 3;
            int k0  = (e & 7) * 4;
            int row = c & 127;
            int gk  = ((c >> 7) << 7) + kc * 32 + k0;
            float4 w = *(const float4*)(W1 + row * 256 + gk);
            *(float2*)&Ws2[(k0 + 0) * WS2_LD + 2 * c] = make_float2(w.x, w.x);
            *(float2*)&Ws2[(k0 + 1) * WS2_LD + 2 * c] = make_float2(w.y, w.y);
            *(float2*)&Ws2[(k0 + 2) * WS2_LD + 2 * c] = make_float2(w.z, w.z);
            *(float2*)&Ws2[(k0 + 3) * WS2_LD + 2 * c] = make_float2(w.w, w.w);
        }
        __syncthreads();

#pragma unroll 4
        for (int k = 0; k < 32; k++) {
            unsigned long long a2[8];
            const float* hrow = HsT + k * HST_LD + 16 * ty;
#pragma unroll
            for (int p = 0; p < 8; p++)
                a2[p] = *(const unsigned long long*)(hrow + 2 * p);

            const float* wrow = Ws2 + k * WS2_LD + 2 * tx;
#pragma unroll
            for (int j = 0; j < 8; j++) {
                unsigned long long b2 = *(const unsigned long long*)(wrow + 64 * j);
#pragma unroll
                for (int p = 0; p < 8; p++)
                    asm("fma.rn.f32x2 %0, %1, %2, %0;"
                        : "+l"(acc2[p][j]) : "l"(a2[p]), "l"(b2));
            }
        }
    }

    // ---- epilogue: fold b1 into U cols; convert to fp16 stores ----
    float b1r[4];
#pragma unroll
    for (int j = 0; j < 4; j++) b1r[j] = __ldg(b1 + tx + 32 * j);

#pragma unroll
    for (int p = 0; p < 8; p++) {
        int r0 = n0 + 16 * ty + 2 * p;
#pragma unroll
        for (int hlf = 0; hlf < 2; hlf++) {
            int n = r0 + hlf;
            if (n < n_nodes) {
                __half* __restrict__ urow = g_U + (size_t)n * HF;
                __half* __restrict__ vrow = g_V + (size_t)n * HF;
#pragma unroll
                for (int j = 0; j < 8; j++) {
                    float val = ((const float*)&acc2[p][j])[hlf];
                    int c = tx + 32 * j;
                    if (j < 4) urow[c]       = __float2half_rn(val + b1r[j]);
                    else       vrow[c - 128] = __float2half_rn(val);
                }
            }
        }
    }
}

// ---------------------------------------------------------------------------
// Kernel 2: per-edge  score = W2 . relu(U'[src] + V[dst]) + b2   (b1 in U')
// fp16 gathers (32B/lane/operand), fp32 math. 4 edges/warp, 8 lanes/edge.
// ---------------------------------------------------------------------------
__global__ __launch_bounds__(256) void edge_score_kernel(
    const void* __restrict__ src_raw,
    const void* __restrict__ dst_raw,
    const float* __restrict__ W2,
    const float* __restrict__ b2,
    float* __restrict__ out,
    int n_edges,
    int n_nodes)
{
    __shared__ int s_is64;
    if (threadIdx.x == 0) {
        // If genuinely int64 (indices < 50000), every high word is 0.
        const unsigned int* p = (const unsigned int*)src_raw;
        int slots = n_edges >> 1; if (slots > 64) slots = 64;
        unsigned int acc = 0;
        for (int i = 0; i < slots; i++) acc |= p[2 * i + 1];
        s_is64 = (acc == 0u) ? 1 : 0;
    }
    __syncthreads();
    const int is64 = s_is64;

    const int lane = threadIdx.x & 31;
    const int q    = lane >> 3;               // edge slot within warp (0..3)
    const int t    = lane & 7;                // sub-lane within edge (0..7)
    const int warp   = (blockIdx.x * blockDim.x + threadIdx.x) >> 5;
    const int nwarps = (gridDim.x * blockDim.x) >> 5;

    // Lane's 16 W2 coefficients (features 16t .. 16t+15)
    float w2r[16];
#pragma unroll
    for (int m = 0; m < 4; m++) {
        float4 w = ((const float4*)W2)[4 * t + m];
        w2r[4 * m + 0] = w.x; w2r[4 * m + 1] = w.y;
        w2r[4 * m + 2] = w.z; w2r[4 * m + 3] = w.w;
    }
    const float b2v = __ldg(b2);

    const int*       src32 = (const int*)src_raw;
    const int*       dst32 = (const int*)dst_raw;
    const long long* src64 = (const long long*)src_raw;
    const long long* dst64 = (const long long*)dst_raw;

    const int n_iter = (n_edges + 3) >> 2;
    for (int it = warp; it < n_iter; it += nwarps) {
        const int e = it * 4 + q;
        const bool live = (e < n_edges);

        int s = 0, d = 0;
        if (live) {
            if (is64) {
                s = (int)__ldg(src64 + e);
                d = (int)__ldg(dst64 + e);
            } else {
                s = __ldg(src32 + e);
                d = __ldg(dst32 + e);
            }
        }
        unsigned int su = ((unsigned int)s < (unsigned int)n_nodes) ? (unsigned int)s : 0u;
        unsigned int du = ((unsigned int)d < (unsigned int)n_nodes) ? (unsigned int)d : 0u;

        // Lane covers 16 halves = 2 uint4 per operand row
        const uint4* urow = (const uint4*)(g_U + (size_t)su * HF);
        const uint4* vrow = (const uint4*)(g_V + (size_t)du * HF);
        uint4 ua[2], va[2];
        ua[0] = urow[2 * t]; ua[1] = urow[2 * t + 1];
        va[0] = vrow[2 * t]; va[1] = vrow[2 * t + 1];

        float acc = 0.f;
#pragma unroll
        for (int b = 0; b < 2; b++) {
            const __half2* up = (const __half2*)&ua[b];
            const __half2* vp = (const __half2*)&va[b];
#pragma unroll
            for (int i = 0; i < 4; i++) {
                float2 uf = __half22float2(up[i]);
                float2 vf = __half22float2(vp[i]);
                int base = b * 8 + i * 2;
                acc = fmaf(fmaxf(uf.x + vf.x, 0.f), w2r[base + 0], acc);
                acc = fmaf(fmaxf(uf.y + vf.y, 0.f), w2r[base + 1], acc);
            }
        }
        acc += __shfl_xor_sync(0xffffffffu, acc, 1);
        acc += __shfl_xor_sync(0xffffffffu, acc, 2);
        acc += __shfl_xor_sync(0xffffffffu, acc, 4);

        if (t == 0 && live) out[e] = acc + b2v;
    }
}

// ---------------------------------------------------------------------------
// Launch
// ---------------------------------------------------------------------------
extern "C" void kernel_launch(void* const* d_in, const int* in_sizes, int n_in,
                              void* d_out, int out_size)
{
    const float* h   = (const float*)d_in[0];
    const void*  src = d_in[1];
    const void*  dst = d_in[2];
    const float* W1  = (const float*)d_in[3];
    const float* b1  = (const float*)d_in[4];
    const float* W2  = (const float*)d_in[5];
    const float* b2  = (const float*)d_in[6];
    float* out = (float*)d_out;

    const int n_nodes = in_sizes[0] / HF;
    const int n_edges = in_sizes[1];
    const int n_tiles = (n_nodes + 127) / 128;

    static int smem_set = 0;
    if (!smem_set) {
        cudaFuncSetAttribute(node_gemm_kernel,
                             cudaFuncAttributeMaxDynamicSharedMemorySize, GEMM_SMEM);
        smem_set = 1;
    }
    node_gemm_kernel<<<n_tiles, 256, GEMM_SMEM>>>(h, W1, b1, n_nodes);
    edge_score_kernel<<<1184, 256>>>(src, dst, W2, b2, out, n_edges, n_nodes);
}

// round 8
// speedup vs baseline: 1.8027x; 1.4811x over previous
#include <cuda_runtime.h>
#include <cuda_fp16.h>
#include <cuda_bf16.h>
#include <cstdint>

#define NNODES_MAX 50000
#define HF 128

// U[n][j] = b1[j] + sum_k W1[j][k]*h[n][k],  V[n][j] = sum_k W1[j][128+k]*h[n][k]
// fp16 storage: halves edge-phase L2 bytes; GEMM accum is fp32.
__device__ __half g_U[NNODES_MAX * HF];
__device__ __half g_V[NNODES_MAX * HF];

__device__ __forceinline__ uint32_t smem_u32(const void* p) {
    uint32_t a;
    asm("{ .reg .u64 t; cvta.to.shared.u64 t, %1; cvt.u32.u64 %0, t; }"
        : "=r"(a) : "l"(p));
    return a;
}
__device__ __forceinline__ void ldsm4(uint32_t* r, uint32_t addr) {
    asm volatile("ldmatrix.sync.aligned.m8n8.x4.shared.b16 {%0,%1,%2,%3}, [%4];"
                 : "=r"(r[0]), "=r"(r[1]), "=r"(r[2]), "=r"(r[3]) : "r"(addr));
}
__device__ __forceinline__ void mma_bf16(float* d, const uint32_t* a, const uint32_t* b) {
    asm volatile(
        "mma.sync.aligned.m16n8k16.row.col.f32.bf16.bf16.f32 "
        "{%0,%1,%2,%3}, {%4,%5,%6,%7}, {%8,%9}, {%0,%1,%2,%3};"
        : "+f"(d[0]), "+f"(d[1]), "+f"(d[2]), "+f"(d[3])
        : "r"(a[0]), "r"(a[1]), "r"(a[2]), "r"(a[3]), "r"(b[0]), "r"(b[1]));
}

// smem: rows padded to 80B (40 bf16) -> ldmatrix phase-conflict-free (20r mod 32 distinct)
#define ROWB 80
#define S_AH 0
#define S_AL 10240
#define S_BH 20480
#define S_BL 30720

// ---------------------------------------------------------------------------
// Kernel 1: node GEMM via mma.sync bf16, 3-pass error compensation.
// blockIdx.x = 2*tile + type (0=U, 1=V). CTA: 128 nodes x 128 cols, 8 warps.
// ---------------------------------------------------------------------------
__global__ __launch_bounds__(256, 1) void node_gemm_mma(
    const float* __restrict__ h,
    const float* __restrict__ W1,
    const float* __restrict__ b1,
    int n_nodes)
{
    __shared__ __align__(16) char smc[40960];
    const uint32_t sb = smem_u32(smc);

    const int tid  = threadIdx.x;
    const int wid  = tid >> 5;
    const int lane = tid & 31;
    const int type = blockIdx.x & 1;
    const int n0   = (blockIdx.x >> 1) * 128;

    const int warp_m = (wid & 3) * 32;   // 4 warps over rows
    const int warp_n = (wid >> 2) * 64;  // 2 warps over cols

    float acc[2][8][4];
#pragma unroll
    for (int mt = 0; mt < 2; mt++)
#pragma unroll
        for (int nt = 0; nt < 8; nt++)
#pragma unroll
            for (int i = 0; i < 4; i++) acc[mt][nt][i] = 0.f;

    const float* wsrc = W1 + type * 128;

    for (int kc = 0; kc < 4; kc++) {
        __syncthreads();
        // ---- fill A (h rows, bf16 hi/lo) : 128 rows x 32 k ----
#pragma unroll
        for (int e = tid; e < 1024; e += 256) {
            int r = e >> 3, q = e & 7;
            int n = n0 + r;
            float4 v = make_float4(0.f, 0.f, 0.f, 0.f);
            if (n < n_nodes)
                v = *(const float4*)(h + (size_t)n * HF + kc * 32 + q * 4);
            __nv_bfloat16 bx = __float2bfloat16_rn(v.x), by = __float2bfloat16_rn(v.y);
            __nv_bfloat16 bz = __float2bfloat16_rn(v.z), bw = __float2bfloat16_rn(v.w);
            __nv_bfloat16 lx = __float2bfloat16_rn(v.x - __bfloat162float(bx));
            __nv_bfloat16 ly = __float2bfloat16_rn(v.y - __bfloat162float(by));
            __nv_bfloat16 lz = __float2bfloat16_rn(v.z - __bfloat162float(bz));
            __nv_bfloat16 lw = __float2bfloat16_rn(v.w - __bfloat162float(bw));
            __nv_bfloat162 h01(bx, by), h23(bz, bw), l01(lx, ly), l23(lz, lw);
            int off = r * ROWB + q * 8;
            *(uint2*)(smc + S_AH + off) = make_uint2(*(uint32_t*)&h01, *(uint32_t*)&h23);
            *(uint2*)(smc + S_AL + off) = make_uint2(*(uint32_t*)&l01, *(uint32_t*)&l23);
        }
        // ---- fill B (W rows = output cols, bf16 hi/lo) : 128 rows x 32 k ----
#pragma unroll
        for (int e = tid; e < 1024; e += 256) {
            int r = e >> 3, q = e & 7;
            float4 v = *(const float4*)(wsrc + (size_t)r * 256 + kc * 32 + q * 4);
            __nv_bfloat16 bx = __float2bfloat16_rn(v.x), by = __float2bfloat16_rn(v.y);
            __nv_bfloat16 bz = __float2bfloat16_rn(v.z), bw = __float2bfloat16_rn(v.w);
            __nv_bfloat16 lx = __float2bfloat16_rn(v.x - __bfloat162float(bx));
            __nv_bfloat16 ly = __float2bfloat16_rn(v.y - __bfloat162float(by));
            __nv_bfloat16 lz = __float2bfloat16_rn(v.z - __bfloat162float(bz));
            __nv_bfloat16 lw = __float2bfloat16_rn(v.w - __bfloat162float(bw));
            __nv_bfloat162 h01(bx, by), h23(bz, bw), l01(lx, ly), l23(lz, lw);
            int off = r * ROWB + q * 8;
            *(uint2*)(smc + S_BH + off) = make_uint2(*(uint32_t*)&h01, *(uint32_t*)&h23);
            *(uint2*)(smc + S_BL + off) = make_uint2(*(uint32_t*)&l01, *(uint32_t*)&l23);
        }
        __syncthreads();

#pragma unroll
        for (int ks = 0; ks < 2; ks++) {
            uint32_t ah[2][4], al[2][4];
#pragma unroll
            for (int mt = 0; mt < 2; mt++) {
                int row = warp_m + mt * 16 + (lane & 15);
                uint32_t addr = sb + row * ROWB + ks * 32 + ((lane >> 4) & 1) * 16;
                ldsm4(ah[mt], addr + S_AH);
                ldsm4(al[mt], addr + S_AL);
            }
#pragma unroll
            for (int np = 0; np < 4; np++) {
                int r = warp_n + np * 16 + (lane & 7) + ((lane >> 4) & 1) * 8;
                uint32_t addr = sb + r * ROWB + ks * 32 + ((lane >> 3) & 1) * 16;
                uint32_t bh[4], bl[4];
                ldsm4(bh, addr + S_BH);
                ldsm4(bl, addr + S_BL);
#pragma unroll
                for (int mt = 0; mt < 2; mt++) {
                    mma_bf16(acc[mt][2 * np],     ah[mt], bh);
                    mma_bf16(acc[mt][2 * np + 1], ah[mt], bh + 2);
                    mma_bf16(acc[mt][2 * np],     ah[mt], bl);
                    mma_bf16(acc[mt][2 * np + 1], ah[mt], bl + 2);
                    mma_bf16(acc[mt][2 * np],     al[mt], bh);
                    mma_bf16(acc[mt][2 * np + 1], al[mt], bh + 2);
                }
            }
        }
    }

    // ---- epilogue: fold b1 (type 0), fp16 stores ----
    const int g = lane >> 2, tig = lane & 3;
    __half* __restrict__ dest = type ? g_V : g_U;

#pragma unroll
    for (int nt = 0; nt < 8; nt++) {
        int col = warp_n + nt * 8 + 2 * tig;
        float bx = 0.f, by = 0.f;
        if (type == 0) { bx = __ldg(b1 + col); by = __ldg(b1 + col + 1); }
#pragma unroll
        for (int mt = 0; mt < 2; mt++) {
            int r0 = n0 + warp_m + mt * 16 + g;
            if (r0 < n_nodes)
                *(__half2*)(dest + (size_t)r0 * HF + col) =
                    __floats2half2_rn(acc[mt][nt][0] + bx, acc[mt][nt][1] + by);
            int r1 = r0 + 8;
            if (r1 < n_nodes)
                *(__half2*)(dest + (size_t)r1 * HF + col) =
                    __floats2half2_rn(acc[mt][nt][2] + bx, acc[mt][nt][3] + by);
        }
    }
}

// ---------------------------------------------------------------------------
// Kernel 2: per-edge  score = W2 . relu(U'[src] + V[dst]) + b2   (b1 in U')
// fp16 gathers (32B/lane/operand), fp32 math. 4 edges/warp, 8 lanes/edge.
// ---------------------------------------------------------------------------
__global__ __launch_bounds__(256) void edge_score_kernel(
    const void* __restrict__ src_raw,
    const void* __restrict__ dst_raw,
    const float* __restrict__ W2,
    const float* __restrict__ b2,
    float* __restrict__ out,
    int n_edges,
    int n_nodes)
{
    __shared__ int s_is64;
    if (threadIdx.x == 0) {
        const unsigned int* p = (const unsigned int*)src_raw;
        int slots = n_edges >> 1; if (slots > 64) slots = 64;
        unsigned int acc = 0;
        for (int i = 0; i < slots; i++) acc |= p[2 * i + 1];
        s_is64 = (acc == 0u) ? 1 : 0;
    }
    __syncthreads();
    const int is64 = s_is64;

    const int lane = threadIdx.x & 31;
    const int q    = lane >> 3;
    const int t    = lane & 7;
    const int warp   = (blockIdx.x * blockDim.x + threadIdx.x) >> 5;
    const int nwarps = (gridDim.x * blockDim.x) >> 5;

    float w2r[16];
#pragma unroll
    for (int m = 0; m < 4; m++) {
        float4 w = ((const float4*)W2)[4 * t + m];
        w2r[4 * m + 0] = w.x; w2r[4 * m + 1] = w.y;
        w2r[4 * m + 2] = w.z; w2r[4 * m + 3] = w.w;
    }
    const float b2v = __ldg(b2);

    const int*       src32 = (const int*)src_raw;
    const int*       dst32 = (const int*)dst_raw;
    const long long* src64 = (const long long*)src_raw;
    const long long* dst64 = (const long long*)dst_raw;

    const int n_iter = (n_edges + 3) >> 2;
    for (int it = warp; it < n_iter; it += nwarps) {
        const int e = it * 4 + q;
        const bool live = (e < n_edges);

        int s = 0, d = 0;
        if (live) {
            if (is64) {
                s = (int)__ldg(src64 + e);
                d = (int)__ldg(dst64 + e);
            } else {
                s = __ldg(src32 + e);
                d = __ldg(dst32 + e);
            }
        }
        unsigned int su = ((unsigned int)s < (unsigned int)n_nodes) ? (unsigned int)s : 0u;
        unsigned int du = ((unsigned int)d < (unsigned int)n_nodes) ? (unsigned int)d : 0u;

        const uint4* urow = (const uint4*)(g_U + (size_t)su * HF);
        const uint4* vrow = (const uint4*)(g_V + (size_t)du * HF);
        uint4 ua[2], va[2];
        ua[0] = urow[2 * t]; ua[1] = urow[2 * t + 1];
        va[0] = vrow[2 * t]; va[1] = vrow[2 * t + 1];

        float acc = 0.f;
#pragma unroll
        for (int b = 0; b < 2; b++) {
            const __half2* up = (const __half2*)&ua[b];
            const __half2* vp = (const __half2*)&va[b];
#pragma unroll
            for (int i = 0; i < 4; i++) {
                float2 uf = __half22float2(up[i]);
                float2 vf = __half22float2(vp[i]);
                int base = b * 8 + i * 2;
                acc = fmaf(fmaxf(uf.x + vf.x, 0.f), w2r[base + 0], acc);
                acc = fmaf(fmaxf(uf.y + vf.y, 0.f), w2r[base + 1], acc);
            }
        }
        acc += __shfl_xor_sync(0xffffffffu, acc, 1);
        acc += __shfl_xor_sync(0xffffffffu, acc, 2);
        acc += __shfl_xor_sync(0xffffffffu, acc, 4);

        if (t == 0 && live) out[e] = acc + b2v;
    }
}

// ---------------------------------------------------------------------------
// Launch
// ---------------------------------------------------------------------------
extern "C" void kernel_launch(void* const* d_in, const int* in_sizes, int n_in,
                              void* d_out, int out_size)
{
    const float* h   = (const float*)d_in[0];
    const void*  src = d_in[1];
    const void*  dst = d_in[2];
    const float* W1  = (const float*)d_in[3];
    const float* b1  = (const float*)d_in[4];
    const float* W2  = (const float*)d_in[5];
    const float* b2  = (const float*)d_in[6];
    float* out = (float*)d_out;

    const int n_nodes = in_sizes[0] / HF;
    const int n_edges = in_sizes[1];
    const int n_tiles = (n_nodes + 127) / 128;

    node_gemm_mma<<<2 * n_tiles, 256>>>(h, W1, b1, n_nodes);
    edge_score_kernel<<<1184, 256>>>(src, dst, W2, b2, out, n_edges, n_nodes);
}

// round 9
// speedup vs baseline: 2.0946x; 1.1620x over previous
#include <cuda_runtime.h>
#include <cuda_fp16.h>
#include <cstdint>

#define NNODES_MAX 50000
#define HF 128

// U[n][j] = b1[j] + sum_k W1[j][k]*h[n][k],  V[n][j] = sum_k W1[j][128+k]*h[n][k]
__device__ __half g_U[NNODES_MAX * HF];
__device__ __half g_V[NNODES_MAX * HF];

__device__ __forceinline__ uint32_t smem_u32(const void* p) {
    uint32_t a;
    asm("{ .reg .u64 t; cvta.to.shared.u64 t, %1; cvt.u32.u64 %0, t; }"
        : "=r"(a) : "l"(p));
    return a;
}
__device__ __forceinline__ void ldsm4(uint32_t* r, uint32_t addr) {
    asm volatile("ldmatrix.sync.aligned.m8n8.x4.shared.b16 {%0,%1,%2,%3}, [%4];"
                 : "=r"(r[0]), "=r"(r[1]), "=r"(r[2]), "=r"(r[3]) : "r"(addr));
}
__device__ __forceinline__ void mma_f16(float* d, const uint32_t* a, const uint32_t* b) {
    asm volatile(
        "mma.sync.aligned.m16n8k16.row.col.f32.f16.f16.f32 "
        "{%0,%1,%2,%3}, {%4,%5,%6,%7}, {%8,%9}, {%0,%1,%2,%3};"
        : "+f"(d[0]), "+f"(d[1]), "+f"(d[2]), "+f"(d[3])
        : "r"(a[0]), "r"(a[1]), "r"(a[2]), "r"(a[3]), "r"(b[0]), "r"(b[1]));
}

// smem rows padded to 80B -> ldmatrix phase-conflict-free
#define ROWB 80
#define S_AH 0
#define S_AL 10240
#define S_BH 20480   // 256 rows x 80B = 20480

// ---------------------------------------------------------------------------
// Kernel 1: node GEMM via mma.sync fp16, 2-pass split (Ah*Bh + Al*Bh).
// One CTA = 128 nodes x 256 cols (U and V together). 512 threads, 16 warps.
// ---------------------------------------------------------------------------
__global__ __launch_bounds__(512, 1) void node_gemm_mma(
    const float* __restrict__ h,
    const float* __restrict__ W1,
    const float* __restrict__ b1,
    int n_nodes)
{
    __shared__ __align__(16) char smc[40960];
    const uint32_t sb = smem_u32(smc);

    const int tid  = threadIdx.x;
    const int wid  = tid >> 5;
    const int lane = tid & 31;
    const int n0   = blockIdx.x * 128;

    const int warp_m = (wid & 3) * 32;    // 4 warps over 128 rows
    const int warp_n = (wid >> 2) * 64;   // 4 warps over 256 cols

    float acc[2][8][4];
#pragma unroll
    for (int mt = 0; mt < 2; mt++)
#pragma unroll
        for (int nt = 0; nt < 8; nt++)
#pragma unroll
            for (int i = 0; i < 4; i++) acc[mt][nt][i] = 0.f;

    for (int kc = 0; kc < 4; kc++) {
        __syncthreads();
        // ---- fill A (h tile, fp16 hi/lo): 128 rows x 32 k, 1024 float4 units ----
#pragma unroll
        for (int e = tid; e < 1024; e += 512) {
            int r = e >> 3, q = e & 7;
            int n = n0 + r;
            float4 v = make_float4(0.f, 0.f, 0.f, 0.f);
            if (n < n_nodes)
                v = *(const float4*)(h + (size_t)n * HF + kc * 32 + q * 4);
            __half hx = __float2half_rn(v.x), hy = __float2half_rn(v.y);
            __half hz = __float2half_rn(v.z), hw = __float2half_rn(v.w);
            __half lx = __float2half_rn(v.x - __half2float(hx));
            __half ly = __float2half_rn(v.y - __half2float(hy));
            __half lz = __float2half_rn(v.z - __half2float(hz));
            __half lw = __float2half_rn(v.w - __half2float(hw));
            __half2 h01(hx, hy), h23(hz, hw), l01(lx, ly), l23(lz, lw);
            int off = r * ROWB + q * 8;
            *(uint2*)(smc + S_AH + off) = make_uint2(*(uint32_t*)&h01, *(uint32_t*)&h23);
            *(uint2*)(smc + S_AL + off) = make_uint2(*(uint32_t*)&l01, *(uint32_t*)&l23);
        }
        // ---- fill B (hi only): 256 rows (output cols) x 32 k, 2048 units ----
#pragma unroll
        for (int e = tid; e < 2048; e += 512) {
            int c = e >> 3, q = e & 7;   // c = output col 0..255
            const float* wp = W1 + (size_t)(c & 127) * 256 + ((c >> 7) << 7) + kc * 32 + q * 4;
            float4 v = *(const float4*)wp;
            __half2 h01(__float2half_rn(v.x), __float2half_rn(v.y));
            __half2 h23(__float2half_rn(v.z), __float2half_rn(v.w));
            *(uint2*)(smc + S_BH + c * ROWB + q * 8) =
                make_uint2(*(uint32_t*)&h01, *(uint32_t*)&h23);
        }
        __syncthreads();

#pragma unroll
        for (int ks = 0; ks < 2; ks++) {
            uint32_t ah[2][4], al[2][4];
#pragma unroll
            for (int mt = 0; mt < 2; mt++) {
                int row = warp_m + mt * 16 + (lane & 15);
                uint32_t addr = sb + row * ROWB + ks * 32 + ((lane >> 4) & 1) * 16;
                ldsm4(ah[mt], addr + S_AH);
                ldsm4(al[mt], addr + S_AL);
            }
#pragma unroll
            for (int np = 0; np < 4; np++) {
                int r = warp_n + np * 16 + (lane & 7) + ((lane >> 4) & 1) * 8;
                uint32_t addr = sb + r * ROWB + ks * 32 + ((lane >> 3) & 1) * 16;
                uint32_t bh[4];
                ldsm4(bh, addr + S_BH);
#pragma unroll
                for (int mt = 0; mt < 2; mt++) {
                    mma_f16(acc[mt][2 * np],     ah[mt], bh);
                    mma_f16(acc[mt][2 * np + 1], ah[mt], bh + 2);
                    mma_f16(acc[mt][2 * np],     al[mt], bh);
                    mma_f16(acc[mt][2 * np + 1], al[mt], bh + 2);
                }
            }
        }
    }

    // ---- epilogue: cols <128 -> U (+b1), >=128 -> V; fp16 stores ----
    const int g = lane >> 2, tig = lane & 3;
#pragma unroll
    for (int nt = 0; nt < 8; nt++) {
        int col = warp_n + nt * 8 + 2 * tig;
        const bool isU = (col < 128);
        __half* __restrict__ dest = isU ? g_U : g_V;
        int cc = isU ? col : (col - 128);
        float bx = 0.f, by = 0.f;
        if (isU) { bx = __ldg(b1 + col); by = __ldg(b1 + col + 1); }
#pragma unroll
        for (int mt = 0; mt < 2; mt++) {
            int r0 = n0 + warp_m + mt * 16 + g;
            if (r0 < n_nodes)
                *(__half2*)(dest + (size_t)r0 * HF + cc) =
                    __floats2half2_rn(acc[mt][nt][0] + bx, acc[mt][nt][1] + by);
            int r1 = r0 + 8;
            if (r1 < n_nodes)
                *(__half2*)(dest + (size_t)r1 * HF + cc) =
                    __floats2half2_rn(acc[mt][nt][2] + bx, acc[mt][nt][3] + by);
        }
    }
}

// ---------------------------------------------------------------------------
// Kernel 2: per-edge  score = W2 . relu(U'[src] + V[dst]) + b2   (b1 in U')
// fp16 gathers; half2 add+relu; fp32 dot. 4 edges/warp, 8 lanes/edge.
// ---------------------------------------------------------------------------
__global__ __launch_bounds__(256) void edge_score_kernel(
    const void* __restrict__ src_raw,
    const void* __restrict__ dst_raw,
    const float* __restrict__ W2,
    const float* __restrict__ b2,
    float* __restrict__ out,
    int n_edges,
    int n_nodes)
{
    __shared__ int s_is64;
    if (threadIdx.x == 0) {
        const unsigned int* p = (const unsigned int*)src_raw;
        int slots = n_edges >> 1; if (slots > 64) slots = 64;
        unsigned int acc = 0;
        for (int i = 0; i < slots; i++) acc |= p[2 * i + 1];
        s_is64 = (acc == 0u) ? 1 : 0;
    }
    __syncthreads();
    const int is64 = s_is64;

    const int lane = threadIdx.x & 31;
    const int q    = lane >> 3;
    const int t    = lane & 7;
    const int warp   = (blockIdx.x * blockDim.x + threadIdx.x) >> 5;
    const int nwarps = (gridDim.x * blockDim.x) >> 5;

    float w2r[16];
#pragma unroll
    for (int m = 0; m < 4; m++) {
        float4 w = ((const float4*)W2)[4 * t + m];
        w2r[4 * m + 0] = w.x; w2r[4 * m + 1] = w.y;
        w2r[4 * m + 2] = w.z; w2r[4 * m + 3] = w.w;
    }
    const float b2v = __ldg(b2);
    const __half2 zero2 = __half2half2(__float2half(0.f));

    const int*       src32 = (const int*)src_raw;
    const int*       dst32 = (const int*)dst_raw;
    const long long* src64 = (const long long*)src_raw;
    const long long* dst64 = (const long long*)dst_raw;

    const int n_iter = (n_edges + 3) >> 2;
    for (int it = warp; it < n_iter; it += nwarps) {
        const int e = it * 4 + q;
        const bool live = (e < n_edges);

        int s = 0, d = 0;
        if (live) {
            if (is64) {
                s = (int)__ldg(src64 + e);
                d = (int)__ldg(dst64 + e);
            } else {
                s = __ldg(src32 + e);
                d = __ldg(dst32 + e);
            }
        }
        unsigned int su = ((unsigned int)s < (unsigned int)n_nodes) ? (unsigned int)s : 0u;
        unsigned int du = ((unsigned int)d < (unsigned int)n_nodes) ? (unsigned int)d : 0u;

        const uint4* urow = (const uint4*)(g_U + (size_t)su * HF);
        const uint4* vrow = (const uint4*)(g_V + (size_t)du * HF);
        uint4 ua[2], va[2];
        ua[0] = urow[2 * t]; ua[1] = urow[2 * t + 1];
        va[0] = vrow[2 * t]; va[1] = vrow[2 * t + 1];

        float acc = 0.f;
#pragma unroll
        for (int b = 0; b < 2; b++) {
            const __half2* up = (const __half2*)&ua[b];
            const __half2* vp = (const __half2*)&va[b];
#pragma unroll
            for (int i = 0; i < 4; i++) {
                __half2 z = __hmax2(__hadd2(up[i], vp[i]), zero2);  // add+relu in fp16
                float2 zf = __half22float2(z);
                int base = b * 8 + i * 2;
                acc = fmaf(zf.x, w2r[base + 0], acc);
                acc = fmaf(zf.y, w2r[base + 1], acc);
            }
        }
        acc += __shfl_xor_sync(0xffffffffu, acc, 1);
        acc += __shfl_xor_sync(0xffffffffu, acc, 2);
        acc += __shfl_xor_sync(0xffffffffu, acc, 4);

        if (t == 0 && live) out[e] = acc + b2v;
    }
}

// ---------------------------------------------------------------------------
// Launch
// ---------------------------------------------------------------------------
extern "C" void kernel_launch(void* const* d_in, const int* in_sizes, int n_in,
                              void* d_out, int out_size)
{
    const float* h   = (const float*)d_in[0];
    const void*  src = d_in[1];
    const void*  dst = d_in[2];
    const float* W1  = (const float*)d_in[3];
    const float* b1  = (const float*)d_in[4];
    const float* W2  = (const float*)d_in[5];
    const float* b2  = (const float*)d_in[6];
    float* out = (float*)d_out;

    const int n_nodes = in_sizes[0] / HF;
    const int n_edges = in_sizes[1];
    const int n_tiles = (n_nodes + 127) / 128;

    node_gemm_mma<<<n_tiles, 512>>>(h, W1, b1, n_nodes);
    edge_score_kernel<<<1184, 256>>>(src, dst, W2, b2, out, n_edges, n_nodes);
}

// round 10
// speedup vs baseline: 2.1470x; 1.0250x over previous
#include <cuda_runtime.h>
#include <cuda_fp16.h>
#include <cstdint>

#define NNODES_MAX 50000
#define HF 128

// U[n][j] = b1[j] + sum_k W1[j][k]*h[n][k],  V[n][j] = sum_k W1[j][128+k]*h[n][k]
__device__ __half g_U[NNODES_MAX * HF];
__device__ __half g_V[NNODES_MAX * HF];

__device__ __forceinline__ uint32_t smem_u32(const void* p) {
    uint32_t a;
    asm("{ .reg .u64 t; cvta.to.shared.u64 t, %1; cvt.u32.u64 %0, t; }"
        : "=r"(a) : "l"(p));
    return a;
}
__device__ __forceinline__ void ldsm4(uint32_t* r, uint32_t addr) {
    asm volatile("ldmatrix.sync.aligned.m8n8.x4.shared.b16 {%0,%1,%2,%3}, [%4];"
                 : "=r"(r[0]), "=r"(r[1]), "=r"(r[2]), "=r"(r[3]) : "r"(addr));
}
__device__ __forceinline__ void mma_f16(float* d, const uint32_t* a, const uint32_t* b) {
    asm volatile(
        "mma.sync.aligned.m16n8k16.row.col.f32.f16.f16.f32 "
        "{%0,%1,%2,%3}, {%4,%5,%6,%7}, {%8,%9}, {%0,%1,%2,%3};"
        : "+f"(d[0]), "+f"(d[1]), "+f"(d[2]), "+f"(d[3])
        : "r"(a[0]), "r"(a[1]), "r"(a[2]), "r"(a[3]), "r"(b[0]), "r"(b[1]));
}

// smem rows padded to 80B -> ldmatrix phase-conflict-free
#define ROWB 80
#define S_AH 0
#define S_AL 10240
#define S_BH 20480   // 256 rows x 80B

// ---------------------------------------------------------------------------
// Kernel 1: node GEMM via mma.sync fp16, 2-pass split (Ah*Bh + Al*Bh).
// One CTA = 128 nodes x 256 cols (U and V together). 512 threads, 16 warps.
// ---------------------------------------------------------------------------
__global__ __launch_bounds__(512, 1) void node_gemm_mma(
    const float* __restrict__ h,
    const float* __restrict__ W1,
    const float* __restrict__ b1,
    int n_nodes)
{
    __shared__ __align__(16) char smc[40960];
    const uint32_t sb = smem_u32(smc);

    const int tid  = threadIdx.x;
    const int wid  = tid >> 5;
    const int lane = tid & 31;
    const int n0   = blockIdx.x * 128;

    const int warp_m = (wid & 3) * 32;    // 4 warps over 128 rows
    const int warp_n = (wid >> 2) * 64;   // 4 warps over 256 cols

    float acc[2][8][4];
#pragma unroll
    for (int mt = 0; mt < 2; mt++)
#pragma unroll
        for (int nt = 0; nt < 8; nt++)
#pragma unroll
            for (int i = 0; i < 4; i++) acc[mt][nt][i] = 0.f;

    for (int kc = 0; kc < 4; kc++) {
        __syncthreads();
        // ---- fill A (h tile, fp16 hi/lo): 128 rows x 32 k ----
#pragma unroll
        for (int e = tid; e < 1024; e += 512) {
            int r = e >> 3, q = e & 7;
            int n = n0 + r;
            float4 v = make_float4(0.f, 0.f, 0.f, 0.f);
            if (n < n_nodes)
                v = *(const float4*)(h + (size_t)n * HF + kc * 32 + q * 4);
            __half hx = __float2half_rn(v.x), hy = __float2half_rn(v.y);
            __half hz = __float2half_rn(v.z), hw = __float2half_rn(v.w);
            __half lx = __float2half_rn(v.x - __half2float(hx));
            __half ly = __float2half_rn(v.y - __half2float(hy));
            __half lz = __float2half_rn(v.z - __half2float(hz));
            __half lw = __float2half_rn(v.w - __half2float(hw));
            __half2 h01(hx, hy), h23(hz, hw), l01(lx, ly), l23(lz, lw);
            int off = r * ROWB + q * 8;
            *(uint2*)(smc + S_AH + off) = make_uint2(*(uint32_t*)&h01, *(uint32_t*)&h23);
            *(uint2*)(smc + S_AL + off) = make_uint2(*(uint32_t*)&l01, *(uint32_t*)&l23);
        }
        // ---- fill B (hi only): 256 rows (output cols) x 32 k ----
#pragma unroll
        for (int e = tid; e < 2048; e += 512) {
            int c = e >> 3, q = e & 7;
            const float* wp = W1 + (size_t)(c & 127) * 256 + ((c >> 7) << 7) + kc * 32 + q * 4;
            float4 v = *(const float4*)wp;
            __half2 h01(__float2half_rn(v.x), __float2half_rn(v.y));
            __half2 h23(__float2half_rn(v.z), __float2half_rn(v.w));
            *(uint2*)(smc + S_BH + c * ROWB + q * 8) =
                make_uint2(*(uint32_t*)&h01, *(uint32_t*)&h23);
        }
        __syncthreads();

#pragma unroll
        for (int ks = 0; ks < 2; ks++) {
            uint32_t ah[2][4], al[2][4];
#pragma unroll
            for (int mt = 0; mt < 2; mt++) {
                int row = warp_m + mt * 16 + (lane & 15);
                uint32_t addr = sb + row * ROWB + ks * 32 + ((lane >> 4) & 1) * 16;
                ldsm4(ah[mt], addr + S_AH);
                ldsm4(al[mt], addr + S_AL);
            }
#pragma unroll
            for (int np = 0; np < 4; np++) {
                int r = warp_n + np * 16 + (lane & 7) + ((lane >> 4) & 1) * 8;
                uint32_t addr = sb + r * ROWB + ks * 32 + ((lane >> 3) & 1) * 16;
                uint32_t bh[4];
                ldsm4(bh, addr + S_BH);
#pragma unroll
                for (int mt = 0; mt < 2; mt++) {
                    mma_f16(acc[mt][2 * np],     ah[mt], bh);
                    mma_f16(acc[mt][2 * np + 1], ah[mt], bh + 2);
                    mma_f16(acc[mt][2 * np],     al[mt], bh);
                    mma_f16(acc[mt][2 * np + 1], al[mt], bh + 2);
                }
            }
        }
    }

    // ---- epilogue: cols <128 -> U (+b1), >=128 -> V; fp16 stores ----
    const int g = lane >> 2, tig = lane & 3;
#pragma unroll
    for (int nt = 0; nt < 8; nt++) {
        int col = warp_n + nt * 8 + 2 * tig;
        const bool isU = (col < 128);
        __half* __restrict__ dest = isU ? g_U : g_V;
        int cc = isU ? col : (col - 128);
        float bx = 0.f, by = 0.f;
        if (isU) { bx = __ldg(b1 + col); by = __ldg(b1 + col + 1); }
#pragma unroll
        for (int mt = 0; mt < 2; mt++) {
            int r0 = n0 + warp_m + mt * 16 + g;
            if (r0 < n_nodes)
                *(__half2*)(dest + (size_t)r0 * HF + cc) =
                    __floats2half2_rn(acc[mt][nt][0] + bx, acc[mt][nt][1] + by);
            int r1 = r0 + 8;
            if (r1 < n_nodes)
                *(__half2*)(dest + (size_t)r1 * HF + cc) =
                    __floats2half2_rn(acc[mt][nt][2] + bx, acc[mt][nt][3] + by);
        }
    }
}

// ---------------------------------------------------------------------------
// Kernel 2: per-edge  score = W2 . relu(U'[src] + V[dst]) + b2   (b1 in U')
// 2 edges/warp, 16 lanes/edge: 1 uint4 U + 1 uint4 V per lane, w2 in 8 regs.
// Low register count -> full occupancy to cover gather latency.
// ---------------------------------------------------------------------------
__global__ __launch_bounds__(256) void edge_score_kernel(
    const void* __restrict__ src_raw,
    const void* __restrict__ dst_raw,
    const float* __restrict__ W2,
    const float* __restrict__ b2,
    float* __restrict__ out,
    int n_edges,
    int n_nodes)
{
    __shared__ int s_is64;
    if (threadIdx.x == 0) {
        const unsigned int* p = (const unsigned int*)src_raw;
        int slots = n_edges >> 1; if (slots > 64) slots = 64;
        unsigned int acc = 0;
        for (int i = 0; i < slots; i++) acc |= p[2 * i + 1];
        s_is64 = (acc == 0u) ? 1 : 0;
    }
    __syncthreads();
    const int is64 = s_is64;

    const int lane = threadIdx.x & 31;
    const int q    = lane >> 4;               // edge slot (0..1)
    const int t    = lane & 15;               // sub-lane within edge (0..15)
    const int warp   = (blockIdx.x * blockDim.x + threadIdx.x) >> 5;
    const int nwarps = (gridDim.x * blockDim.x) >> 5;

    // Lane's 8 W2 coefficients (features 8t .. 8t+7)
    float w2r[8];
    {
        float4 wa = ((const float4*)W2)[2 * t];
        float4 wb = ((const float4*)W2)[2 * t + 1];
        w2r[0] = wa.x; w2r[1] = wa.y; w2r[2] = wa.z; w2r[3] = wa.w;
        w2r[4] = wb.x; w2r[5] = wb.y; w2r[6] = wb.z; w2r[7] = wb.w;
    }
    const float b2v = __ldg(b2);
    const __half2 zero2 = __half2half2(__float2half(0.f));

    const int*       src32 = (const int*)src_raw;
    const int*       dst32 = (const int*)dst_raw;
    const long long* src64 = (const long long*)src_raw;
    const long long* dst64 = (const long long*)dst_raw;

    const int n_iter = (n_edges + 1) >> 1;
    for (int it = warp; it < n_iter; it += nwarps) {
        const int e = it * 2 + q;
        const bool live = (e < n_edges);

        int s = 0, d = 0;
        if (live) {
            if (is64) {
                s = (int)__ldg(src64 + e);
                d = (int)__ldg(dst64 + e);
            } else {
                s = __ldg(src32 + e);
                d = __ldg(dst32 + e);
            }
        }
        unsigned int su = ((unsigned int)s < (unsigned int)n_nodes) ? (unsigned int)s : 0u;
        unsigned int du = ((unsigned int)d < (unsigned int)n_nodes) ? (unsigned int)d : 0u;

        // Lane covers features 8t..8t+7 = 1 uint4 per operand
        uint4 ua = ((const uint4*)(g_U + (size_t)su * HF))[t];
        uint4 va = ((const uint4*)(g_V + (size_t)du * HF))[t];

        const __half2* up = (const __half2*)&ua;
        const __half2* vp = (const __half2*)&va;
        float acc = 0.f;
#pragma unroll
        for (int i = 0; i < 4; i++) {
            __half2 z = __hmax2(__hadd2(up[i], vp[i]), zero2);
            float2 zf = __half22float2(z);
            acc = fmaf(zf.x, w2r[2 * i + 0], acc);
            acc = fmaf(zf.y, w2r[2 * i + 1], acc);
        }
        acc += __shfl_xor_sync(0xffffffffu, acc, 1);
        acc += __shfl_xor_sync(0xffffffffu, acc, 2);
        acc += __shfl_xor_sync(0xffffffffu, acc, 4);
        acc += __shfl_xor_sync(0xffffffffu, acc, 8);

        if (t == 0 && live) out[e] = acc + b2v;
    }
}

// ---------------------------------------------------------------------------
// Launch
// ---------------------------------------------------------------------------
extern "C" void kernel_launch(void* const* d_in, const int* in_sizes, int n_in,
                              void* d_out, int out_size)
{
    const float* h   = (const float*)d_in[0];
    const void*  src = d_in[1];
    const void*  dst = d_in[2];
    const float* W1  = (const float*)d_in[3];
    const float* b1  = (const float*)d_in[4];
    const float* W2  = (const float*)d_in[5];
    const float* b2  = (const float*)d_in[6];
    float* out = (float*)d_out;

    const int n_nodes = in_sizes[0] / HF;
    const int n_edges = in_sizes[1];
    const int n_tiles = (n_nodes + 127) / 128;

    node_gemm_mma<<<n_tiles, 512>>>(h, W1, b1, n_nodes);
    edge_score_kernel<<<1184, 256>>>(src, dst, W2, b2, out, n_edges, n_nodes);
}

// round 12
// speedup vs baseline: 2.2100x; 1.0293x over previous
#include <cuda_runtime.h>
#include <cuda_fp16.h>
#include <cstdint>

#define NNODES_MAX 50000
#define HF 128

// U[n][j] = b1[j] + sum_k W1[j][k]*h[n][k],  V[n][j] = sum_k W1[j][128+k]*h[n][k]
__device__ __half g_U[NNODES_MAX * HF];
__device__ __half g_V[NNODES_MAX * HF];
// W1 pre-converted: g_Bh[c][k] = fp16(W1[c & 127][((c>>7)<<7) + k]), c = output col
__device__ __half g_Bh[256 * 128];

__device__ __forceinline__ uint32_t smem_u32(const void* p) {
    uint32_t a;
    asm("{ .reg .u64 t; cvta.to.shared.u64 t, %1; cvt.u32.u64 %0, t; }"
        : "=r"(a) : "l"(p));
    return a;
}
__device__ __forceinline__ void ldsm4(uint32_t* r, uint32_t addr) {
    asm volatile("ldmatrix.sync.aligned.m8n8.x4.shared.b16 {%0,%1,%2,%3}, [%4];"
                 : "=r"(r[0]), "=r"(r[1]), "=r"(r[2]), "=r"(r[3]) : "r"(addr));
}
__device__ __forceinline__ void mma_f16(float* d, const uint32_t* a, const uint32_t* b) {
    asm volatile(
        "mma.sync.aligned.m16n8k16.row.col.f32.f16.f16.f32 "
        "{%0,%1,%2,%3}, {%4,%5,%6,%7}, {%8,%9}, {%0,%1,%2,%3};"
        : "+f"(d[0]), "+f"(d[1]), "+f"(d[2]), "+f"(d[3])
        : "r"(a[0]), "r"(a[1]), "r"(a[2]), "r"(a[3]), "r"(b[0]), "r"(b[1]));
}
__device__ __forceinline__ void cp_async16(uint32_t dst, const void* src) {
    asm volatile("cp.async.ca.shared.global [%0], [%1], 16;"
                 :: "r"(dst), "l"(src) : "memory");
}

// smem rows: 128 k * 2B = 256B data + 16B pad = 272B -> ldmatrix conflict-free
#define ROWB 272
#define S_AH 0
#define S_AL (128 * ROWB)          // 34816
#define S_B  (2 * 128 * ROWB)      // 69632
#define GEMM_SMEM (2 * 128 * ROWB + 256 * ROWB)   // 139264

// ---------------------------------------------------------------------------
// Kernel 0: one-time W1 -> fp16 conversion (removes per-CTA redundancy)
// ---------------------------------------------------------------------------
__global__ void prep_w1_kernel(const float* __restrict__ W1)
{
    int i = blockIdx.x * blockDim.x + threadIdx.x;   // 0 .. 32767
    if (i < 256 * 128) {
        int c = i >> 7, k = i & 127;
        g_Bh[i] = __float2half_rn(W1[(size_t)(c & 127) * 256 + ((c >> 7) << 7) + k]);
    }
}

// ---------------------------------------------------------------------------
// Kernel 1: node GEMM via mma.sync fp16, 2-pass split (Ah*Bh + Al*Bh).
// Single-pass K: whole tiles in smem. CTA = 128 nodes x 256 cols, 512 thr.
// ---------------------------------------------------------------------------
__global__ __launch_bounds__(512, 1) void node_gemm_mma(
    const float* __restrict__ h,
    const float* __restrict__ b1,
    int n_nodes)
{
    extern __shared__ __align__(16) char smc[];
    const uint32_t sb = smem_u32(smc);

    const int tid  = threadIdx.x;
    const int wid  = tid >> 5;
    const int lane = tid & 31;
    const int n0   = blockIdx.x * 128;

    const int warp_m = (wid & 3) * 32;    // 4 warps over 128 rows
    const int warp_n = (wid >> 2) * 64;   // 4 warps over 256 cols

    // ---- B tile: cp.async copy of pre-converted fp16.
    // 256 rows x 16 chunks of 16B = 4096 copies (8 per thread).
#pragma unroll
    for (int u = tid; u < 4096; u += 512) {
        int c = u >> 4, q = u & 15;       // c = output col row, q = 16B chunk
        cp_async16(sb + S_B + c * ROWB + q * 16, (const char*)g_Bh + c * 256 + q * 16);
    }
    asm volatile("cp.async.commit_group;" ::: "memory");

    // ---- A tile: load h, split fp16 hi/lo.
    // 128 rows x 32 float4 = 4096 units (8 per thread).
#pragma unroll
    for (int u = tid; u < 4096; u += 512) {
        int r = u >> 5, q = u & 31;       // r = node row, q = float4 within row
        int n = n0 + r;
        float4 v = make_float4(0.f, 0.f, 0.f, 0.f);
        if (n < n_nodes)
            v = *(const float4*)(h + (size_t)n * HF + q * 4);
        __half hx = __float2half_rn(v.x), hy = __float2half_rn(v.y);
        __half hz = __float2half_rn(v.z), hw = __float2half_rn(v.w);
        __half lx = __float2half_rn(v.x - __half2float(hx));
        __half ly = __float2half_rn(v.y - __half2float(hy));
        __half lz = __float2half_rn(v.z - __half2float(hz));
        __half lw = __float2half_rn(v.w - __half2float(hw));
        __half2 h01(hx, hy), h23(hz, hw), l01(lx, ly), l23(lz, lw);
        int off = r * ROWB + q * 8;
        *(uint2*)(smc + S_AH + off) = make_uint2(*(uint32_t*)&h01, *(uint32_t*)&h23);
        *(uint2*)(smc + S_AL + off) = make_uint2(*(uint32_t*)&l01, *(uint32_t*)&l23);
    }
    asm volatile("cp.async.wait_all;" ::: "memory");
    __syncthreads();

    float acc[2][8][4];
#pragma unroll
    for (int mt = 0; mt < 2; mt++)
#pragma unroll
        for (int nt = 0; nt < 8; nt++)
#pragma unroll
            for (int i = 0; i < 4; i++) acc[mt][nt][i] = 0.f;

    // ---- MMA sweep: 8 k-steps of 16 ----
#pragma unroll
    for (int ks = 0; ks < 8; ks++) {
        uint32_t ah[2][4], al[2][4];
#pragma unroll
        for (int mt = 0; mt < 2; mt++) {
            int row = warp_m + mt * 16 + (lane & 15);
            uint32_t addr = sb + row * ROWB + ks * 32 + ((lane >> 4) & 1) * 16;
            ldsm4(ah[mt], addr + S_AH);
            ldsm4(al[mt], addr + S_AL);
        }
#pragma unroll
        for (int np = 0; np < 4; np++) {
            int r = warp_n + np * 16 + (lane & 7) + ((lane >> 4) & 1) * 8;
            uint32_t addr = sb + S_B + r * ROWB + ks * 32 + ((lane >> 3) & 1) * 16;
            uint32_t bh[4];
            ldsm4(bh, addr);
#pragma unroll
            for (int mt = 0; mt < 2; mt++) {
                mma_f16(acc[mt][2 * np],     ah[mt], bh);
                mma_f16(acc[mt][2 * np + 1], ah[mt], bh + 2);
                mma_f16(acc[mt][2 * np],     al[mt], bh);
                mma_f16(acc[mt][2 * np + 1], al[mt], bh + 2);
            }
        }
    }

    // ---- epilogue: cols <128 -> U (+b1), >=128 -> V; fp16 stores ----
    const int g = lane >> 2, tig = lane & 3;
#pragma unroll
    for (int nt = 0; nt < 8; nt++) {
        int col = warp_n + nt * 8 + 2 * tig;
        const bool isU = (col < 128);
        __half* __restrict__ dest = isU ? g_U : g_V;
        int cc = isU ? col : (col - 128);
        float bx = 0.f, by = 0.f;
        if (isU) { bx = __ldg(b1 + col); by = __ldg(b1 + col + 1); }
#pragma unroll
        for (int mt = 0; mt < 2; mt++) {
            int r0 = n0 + warp_m + mt * 16 + g;
            if (r0 < n_nodes)
                *(__half2*)(dest + (size_t)r0 * HF + cc) =
                    __floats2half2_rn(acc[mt][nt][0] + bx, acc[mt][nt][1] + by);
            int r1 = r0 + 8;
            if (r1 < n_nodes)
                *(__half2*)(dest + (size_t)r1 * HF + cc) =
                    __floats2half2_rn(acc[mt][nt][2] + bx, acc[mt][nt][3] + by);
        }
    }
}

// ---------------------------------------------------------------------------
// Kernel 2: per-edge  score = W2 . relu(U'[src] + V[dst]) + b2   (b1 in U')
// 2 edges/warp, 16 lanes/edge; low regs -> full occupancy.
// ---------------------------------------------------------------------------
__global__ __launch_bounds__(256) void edge_score_kernel(
    const void* __restrict__ src_raw,
    const void* __restrict__ dst_raw,
    const float* __restrict__ W2,
    const float* __restrict__ b2,
    float* __restrict__ out,
    int n_edges,
    int n_nodes)
{
    __shared__ int s_is64;
    if (threadIdx.x == 0) {
        const unsigned int* p = (const unsigned int*)src_raw;
        int slots = n_edges >> 1; if (slots > 64) slots = 64;
        unsigned int acc = 0;
        for (int i = 0; i < slots; i++) acc |= p[2 * i + 1];
        s_is64 = (acc == 0u) ? 1 : 0;
    }
    __syncthreads();
    const int is64 = s_is64;

    const int lane = threadIdx.x & 31;
    const int q    = lane >> 4;               // edge slot (0..1)
    const int t    = lane & 15;               // sub-lane within edge (0..15)
    const int warp   = (blockIdx.x * blockDim.x + threadIdx.x) >> 5;
    const int nwarps = (gridDim.x * blockDim.x) >> 5;

    float w2r[8];
    {
        float4 wa = ((const float4*)W2)[2 * t];
        float4 wb = ((const float4*)W2)[2 * t + 1];
        w2r[0] = wa.x; w2r[1] = wa.y; w2r[2] = wa.z; w2r[3] = wa.w;
        w2r[4] = wb.x; w2r[5] = wb.y; w2r[6] = wb.z; w2r[7] = wb.w;
    }
    const float b2v = __ldg(b2);
    const __half2 zero2 = __half2half2(__float2half(0.f));

    const int*       src32 = (const int*)src_raw;
    const int*       dst32 = (const int*)dst_raw;
    const long long* src64 = (const long long*)src_raw;
    const long long* dst64 = (const long long*)dst_raw;

    const int n_iter = (n_edges + 1) >> 1;
    for (int it = warp; it < n_iter; it += nwarps) {
        const int e = it * 2 + q;
        const bool live = (e < n_edges);

        int s = 0, d = 0;
        if (live) {
            if (is64) {
                s = (int)__ldg(src64 + e);
                d = (int)__ldg(dst64 + e);
            } else {
                s = __ldg(src32 + e);
                d = __ldg(dst32 + e);
            }
        }
        unsigned int su = ((unsigned int)s < (unsigned int)n_nodes) ? (unsigned int)s : 0u;
        unsigned int du = ((unsigned int)d < (unsigned int)n_nodes) ? (unsigned int)d : 0u;

        uint4 ua = ((const uint4*)(g_U + (size_t)su * HF))[t];
        uint4 va = ((const uint4*)(g_V + (size_t)du * HF))[t];

        const __half2* up = (const __half2*)&ua;
        const __half2* vp = (const __half2*)&va;
        float acc = 0.f;
#pragma unroll
        for (int i = 0; i < 4; i++) {
            __half2 z = __hmax2(__hadd2(up[i], vp[i]), zero2);
            float2 zf = __half22float2(z);
            acc = fmaf(zf.x, w2r[2 * i + 0], acc);
            acc = fmaf(zf.y, w2r[2 * i + 1], acc);
        }
        acc += __shfl_xor_sync(0xffffffffu, acc, 1);
        acc += __shfl_xor_sync(0xffffffffu, acc, 2);
        acc += __shfl_xor_sync(0xffffffffu, acc, 4);
        acc += __shfl_xor_sync(0xffffffffu, acc, 8);

        if (t == 0 && live) out[e] = acc + b2v;
    }
}

// ---------------------------------------------------------------------------
// Launch
// ---------------------------------------------------------------------------
extern "C" void kernel_launch(void* const* d_in, const int* in_sizes, int n_in,
                              void* d_out, int out_size)
{
    const float* h   = (const float*)d_in[0];
    const void*  src = d_in[1];
    const void*  dst = d_in[2];
    const float* W1  = (const float*)d_in[3];
    const float* b1  = (const float*)d_in[4];
    const float* W2  = (const float*)d_in[5];
    const float* b2  = (const float*)d_in[6];
    float* out = (float*)d_out;

    const int n_nodes = in_sizes[0] / HF;
    const int n_edges = in_sizes[1];
    const int n_tiles = (n_nodes + 127) / 128;

    cudaFuncSetAttribute(node_gemm_mma,
                         cudaFuncAttributeMaxDynamicSharedMemorySize, GEMM_SMEM);

    prep_w1_kernel<<<64, 512>>>(W1);
    node_gemm_mma<<<n_tiles, 512, GEMM_SMEM>>>(h, b1, n_nodes);
    edge_score_kernel<<<1184, 256>>>(src, dst, W2, b2, out, n_edges, n_nodes);
}

// round 13
// speedup vs baseline: 2.3324x; 1.0554x over previous
#include <cuda_runtime.h>
#include <cuda_fp16.h>
#include <cstdint>

#define NNODES_MAX 50000
#define HF 128

// U[n][j] = b1[j] + sum_k W1[j][k]*h[n][k],  V[n][j] = sum_k W1[j][128+k]*h[n][k]
__device__ __half g_U[NNODES_MAX * HF];
__device__ __half g_V[NNODES_MAX * HF];

__device__ __forceinline__ uint32_t smem_u32(const void* p) {
    uint32_t a;
    asm("{ .reg .u64 t; cvta.to.shared.u64 t, %1; cvt.u32.u64 %0, t; }"
        : "=r"(a) : "l"(p));
    return a;
}
__device__ __forceinline__ void ldsm4(uint32_t* r, uint32_t addr) {
    asm volatile("ldmatrix.sync.aligned.m8n8.x4.shared.b16 {%0,%1,%2,%3}, [%4];"
                 : "=r"(r[0]), "=r"(r[1]), "=r"(r[2]), "=r"(r[3]) : "r"(addr));
}
__device__ __forceinline__ void mma_f16(float* d, const uint32_t* a, const uint32_t* b) {
    asm volatile(
        "mma.sync.aligned.m16n8k16.row.col.f32.f16.f16.f32 "
        "{%0,%1,%2,%3}, {%4,%5,%6,%7}, {%8,%9}, {%0,%1,%2,%3};"
        : "+f"(d[0]), "+f"(d[1]), "+f"(d[2]), "+f"(d[3])
        : "r"(a[0]), "r"(a[1]), "r"(a[2]), "r"(a[3]), "r"(b[0]), "r"(b[1]));
}

// smem rows: 128 k * 2B = 256B data + 16B pad = 272B -> ldmatrix conflict-free
#define ROWB 272
#define S_AH 0
#define S_AL (128 * ROWB)          // 34816
#define S_B  (2 * 128 * ROWB)      // 69632
#define GEMM_SMEM (2 * 128 * ROWB + 256 * ROWB)   // 139264

// ---------------------------------------------------------------------------
// Kernel 1: persistent node GEMM via mma.sync fp16, 2-pass split (Ah*Bh+Al*Bh).
// Each resident CTA converts B (fp16 of W1) into smem ONCE, then loops over
// 128-node tiles re-filling only the A tile. No prep kernel, no B refills.
// ---------------------------------------------------------------------------
__global__ __launch_bounds__(512, 1) void node_gemm_mma(
    const float* __restrict__ h,
    const float* __restrict__ W1,
    const float* __restrict__ b1,
    int n_nodes,
    int n_tiles)
{
    extern __shared__ __align__(16) char smc[];
    const uint32_t sb = smem_u32(smc);

    const int tid  = threadIdx.x;
    const int wid  = tid >> 5;
    const int lane = tid & 31;

    const int warp_m = (wid & 3) * 32;    // 4 warps over 128 rows
    const int warp_n = (wid >> 2) * 64;   // 4 warps over 256 cols

    // ---- B tile: convert W1 -> fp16 once per CTA.
    // 256 cols x 32 float4 = 8192 units (16 per thread).
#pragma unroll
    for (int u = tid; u < 8192; u += 512) {
        int c = u >> 5, q = u & 31;       // c = output col, q = float4 within k
        const float* wp = W1 + (size_t)(c & 127) * 256 + ((c >> 7) << 7) + q * 4;
        float4 v = *(const float4*)wp;
        __half2 h01(__float2half_rn(v.x), __float2half_rn(v.y));
        __half2 h23(__float2half_rn(v.z), __float2half_rn(v.w));
        *(uint2*)(smc + S_B + c * ROWB + q * 8) =
            make_uint2(*(uint32_t*)&h01, *(uint32_t*)&h23);
    }

    // b1 for this thread's epilogue columns (cols warp_n + nt*8 + 2*tig)
    const int tig = lane & 3;
    float b1x[8], b1y[8];
#pragma unroll
    for (int nt = 0; nt < 8; nt++) {
        int col = warp_n + nt * 8 + 2 * tig;
        b1x[nt] = (col < 128) ? __ldg(b1 + col)     : 0.f;
        b1y[nt] = (col < 128) ? __ldg(b1 + col + 1) : 0.f;
    }

    for (int tile = blockIdx.x; tile < n_tiles; tile += gridDim.x) {
        const int n0 = tile * 128;
        __syncthreads();   // prior ldmatrix reads done before overwriting A

        // ---- A tile: load h, split fp16 hi/lo (8 float4/thread) ----
#pragma unroll
        for (int u = tid; u < 4096; u += 512) {
            int r = u >> 5, q = u & 31;
            int n = n0 + r;
            float4 v = make_float4(0.f, 0.f, 0.f, 0.f);
            if (n < n_nodes)
                v = *(const float4*)(h + (size_t)n * HF + q * 4);
            __half hx = __float2half_rn(v.x), hy = __float2half_rn(v.y);
            __half hz = __float2half_rn(v.z), hw = __float2half_rn(v.w);
            __half lx = __float2half_rn(v.x - __half2float(hx));
            __half ly = __float2half_rn(v.y - __half2float(hy));
            __half lz = __float2half_rn(v.z - __half2float(hz));
            __half lw = __float2half_rn(v.w - __half2float(hw));
            __half2 h01(hx, hy), h23(hz, hw), l01(lx, ly), l23(lz, lw);
            int off = r * ROWB + q * 8;
            *(uint2*)(smc + S_AH + off) = make_uint2(*(uint32_t*)&h01, *(uint32_t*)&h23);
            *(uint2*)(smc + S_AL + off) = make_uint2(*(uint32_t*)&l01, *(uint32_t*)&l23);
        }
        __syncthreads();

        float acc[2][8][4];
#pragma unroll
        for (int mt = 0; mt < 2; mt++)
#pragma unroll
            for (int nt = 0; nt < 8; nt++)
#pragma unroll
                for (int i = 0; i < 4; i++) acc[mt][nt][i] = 0.f;

        // ---- MMA sweep: 8 k-steps of 16 ----
#pragma unroll
        for (int ks = 0; ks < 8; ks++) {
            uint32_t ah[2][4], al[2][4];
#pragma unroll
            for (int mt = 0; mt < 2; mt++) {
                int row = warp_m + mt * 16 + (lane & 15);
                uint32_t addr = sb + row * ROWB + ks * 32 + ((lane >> 4) & 1) * 16;
                ldsm4(ah[mt], addr + S_AH);
                ldsm4(al[mt], addr + S_AL);
            }
#pragma unroll
            for (int np = 0; np < 4; np++) {
                int r = warp_n + np * 16 + (lane & 7) + ((lane >> 4) & 1) * 8;
                uint32_t addr = sb + S_B + r * ROWB + ks * 32 + ((lane >> 3) & 1) * 16;
                uint32_t bh[4];
                ldsm4(bh, addr);
#pragma unroll
                for (int mt = 0; mt < 2; mt++) {
                    mma_f16(acc[mt][2 * np],     ah[mt], bh);
                    mma_f16(acc[mt][2 * np + 1], ah[mt], bh + 2);
                    mma_f16(acc[mt][2 * np],     al[mt], bh);
                    mma_f16(acc[mt][2 * np + 1], al[mt], bh + 2);
                }
            }
        }

        // ---- epilogue: cols <128 -> U (+b1), >=128 -> V; fp16 stores ----
        const int g = lane >> 2;
#pragma unroll
        for (int nt = 0; nt < 8; nt++) {
            int col = warp_n + nt * 8 + 2 * tig;
            const bool isU = (col < 128);
            __half* __restrict__ dest = isU ? g_U : g_V;
            int cc = isU ? col : (col - 128);
#pragma unroll
            for (int mt = 0; mt < 2; mt++) {
                int r0 = n0 + warp_m + mt * 16 + g;
                if (r0 < n_nodes)
                    *(__half2*)(dest + (size_t)r0 * HF + cc) =
                        __floats2half2_rn(acc[mt][nt][0] + b1x[nt],
                                          acc[mt][nt][1] + b1y[nt]);
                int r1 = r0 + 8;
                if (r1 < n_nodes)
                    *(__half2*)(dest + (size_t)r1 * HF + cc) =
                        __floats2half2_rn(acc[mt][nt][2] + b1x[nt],
                                          acc[mt][nt][3] + b1y[nt]);
            }
        }
    }
}

// ---------------------------------------------------------------------------
// Kernel 2: per-edge  score = W2 . relu(U'[src] + V[dst]) + b2   (b1 in U')
// 2 edges/warp, 16 lanes/edge; low regs -> full occupancy.
// ---------------------------------------------------------------------------
__global__ __launch_bounds__(256) void edge_score_kernel(
    const void* __restrict__ src_raw,
    const void* __restrict__ dst_raw,
    const float* __restrict__ W2,
    const float* __restrict__ b2,
    float* __restrict__ out,
    int n_edges,
    int n_nodes)
{
    __shared__ int s_is64;
    if (threadIdx.x == 0) {
        const unsigned int* p = (const unsigned int*)src_raw;
        int slots = n_edges >> 1; if (slots > 64) slots = 64;
        unsigned int acc = 0;
        for (int i = 0; i < slots; i++) acc |= p[2 * i + 1];
        s_is64 = (acc == 0u) ? 1 : 0;
    }
    __syncthreads();
    const int is64 = s_is64;

    const int lane = threadIdx.x & 31;
    const int q    = lane >> 4;               // edge slot (0..1)
    const int t    = lane & 15;               // sub-lane within edge (0..15)
    const int warp   = (blockIdx.x * blockDim.x + threadIdx.x) >> 5;
    const int nwarps = (gridDim.x * blockDim.x) >> 5;

    float w2r[8];
    {
        float4 wa = ((const float4*)W2)[2 * t];
        float4 wb = ((const float4*)W2)[2 * t + 1];
        w2r[0] = wa.x; w2r[1] = wa.y; w2r[2] = wa.z; w2r[3] = wa.w;
        w2r[4] = wb.x; w2r[5] = wb.y; w2r[6] = wb.z; w2r[7] = wb.w;
    }
    const float b2v = __ldg(b2);
    const __half2 zero2 = __half2half2(__float2half(0.f));

    const int*       src32 = (const int*)src_raw;
    const int*       dst32 = (const int*)dst_raw;
    const long long* src64 = (const long long*)src_raw;
    const long long* dst64 = (const long long*)dst_raw;

    const int n_iter = (n_edges + 1) >> 1;
    for (int it = warp; it < n_iter; it += nwarps) {
        const int e = it * 2 + q;
        const bool live = (e < n_edges);

        int s = 0, d = 0;
        if (live) {
            if (is64) {
                s = (int)__ldg(src64 + e);
                d = (int)__ldg(dst64 + e);
            } else {
                s = __ldg(src32 + e);
                d = __ldg(dst32 + e);
            }
        }
        unsigned int su = ((unsigned int)s < (unsigned int)n_nodes) ? (unsigned int)s : 0u;
        unsigned int du = ((unsigned int)d < (unsigned int)n_nodes) ? (unsigned int)d : 0u;

        uint4 ua = ((const uint4*)(g_U + (size_t)su * HF))[t];
        uint4 va = ((const uint4*)(g_V + (size_t)du * HF))[t];

        const __half2* up = (const __half2*)&ua;
        const __half2* vp = (const __half2*)&va;
        float acc = 0.f;
#pragma unroll
        for (int i = 0; i < 4; i++) {
            __half2 z = __hmax2(__hadd2(up[i], vp[i]), zero2);
            float2 zf = __half22float2(z);
            acc = fmaf(zf.x, w2r[2 * i + 0], acc);
            acc = fmaf(zf.y, w2r[2 * i + 1], acc);
        }
        acc += __shfl_xor_sync(0xffffffffu, acc, 1);
        acc += __shfl_xor_sync(0xffffffffu, acc, 2);
        acc += __shfl_xor_sync(0xffffffffu, acc, 4);
        acc += __shfl_xor_sync(0xffffffffu, acc, 8);

        if (t == 0 && live) out[e] = acc + b2v;
    }
}

// ---------------------------------------------------------------------------
// Launch
// ---------------------------------------------------------------------------
extern "C" void kernel_launch(void* const* d_in, const int* in_sizes, int n_in,
                              void* d_out, int out_size)
{
    const float* h   = (const float*)d_in[0];
    const void*  src = d_in[1];
    const void*  dst = d_in[2];
    const float* W1  = (const float*)d_in[3];
    const float* b1  = (const float*)d_in[4];
    const float* W2  = (const float*)d_in[5];
    const float* b2  = (const float*)d_in[6];
    float* out = (float*)d_out;

    const int n_nodes = in_sizes[0] / HF;
    const int n_edges = in_sizes[1];
    const int n_tiles = (n_nodes + 127) / 128;
    const int grid    = (n_tiles < 148) ? n_tiles : 148;

    cudaFuncSetAttribute(node_gemm_mma,
                         cudaFuncAttributeMaxDynamicSharedMemorySize, GEMM_SMEM);

    node_gemm_mma<<<grid, 512, GEMM_SMEM>>>(h, W1, b1, n_nodes, n_tiles);
    edge_score_kernel<<<1184, 256>>>(src, dst, W2, b2, out, n_edges, n_nodes);
}

// round 14
// speedup vs baseline: 2.6441x; 1.1336x over previous
#include <cuda_runtime.h>
#include <cuda_fp16.h>
#include <cstdint>

#define NNODES_MAX 50000
#define HF 128

// U[n][j] = b1[j] + sum_k W1[j][k]*h[n][k],  V[n][j] = sum_k W1[j][128+k]*h[n][k]
__device__ __half g_U[NNODES_MAX * HF];
__device__ __half g_V[NNODES_MAX * HF];

__device__ __forceinline__ uint32_t smem_u32(const void* p) {
    uint32_t a;
    asm("{ .reg .u64 t; cvta.to.shared.u64 t, %1; cvt.u32.u64 %0, t; }"
        : "=r"(a) : "l"(p));
    return a;
}
__device__ __forceinline__ void ldsm4(uint32_t* r, uint32_t addr) {
    asm volatile("ldmatrix.sync.aligned.m8n8.x4.shared.b16 {%0,%1,%2,%3}, [%4];"
                 : "=r"(r[0]), "=r"(r[1]), "=r"(r[2]), "=r"(r[3]) : "r"(addr));
}
__device__ __forceinline__ void mma_f16(float* d, const uint32_t* a, const uint32_t* b) {
    asm volatile(
        "mma.sync.aligned.m16n8k16.row.col.f32.f16.f16.f32 "
        "{%0,%1,%2,%3}, {%4,%5,%6,%7}, {%8,%9}, {%0,%1,%2,%3};"
        : "+f"(d[0]), "+f"(d[1]), "+f"(d[2]), "+f"(d[3])
        : "r"(a[0]), "r"(a[1]), "r"(a[2]), "r"(a[3]), "r"(b[0]), "r"(b[1]));
}

// smem rows: 128 k * 2B = 256B data + 16B pad = 272B -> ldmatrix conflict-free
#define ROWB 272
#define S_A  0
#define S_B  (128 * ROWB)                    // 34816
#define GEMM_SMEM ((128 + 256) * ROWB)       // 104448

// ---------------------------------------------------------------------------
// Kernel 1: persistent node GEMM via mma.sync fp16 (single pass, Ah*Bh).
// Each resident CTA converts B (fp16 of W1) once, then loops over node tiles.
// ---------------------------------------------------------------------------
__global__ __launch_bounds__(512, 1) void node_gemm_mma(
    const float* __restrict__ h,
    const float* __restrict__ W1,
    const float* __restrict__ b1,
    int n_nodes,
    int n_tiles)
{
    extern __shared__ __align__(16) char smc[];
    const uint32_t sb = smem_u32(smc);

    const int tid  = threadIdx.x;
    const int wid  = tid >> 5;
    const int lane = tid & 31;

    const int warp_m = (wid & 3) * 32;    // 4 warps over 128 rows
    const int warp_n = (wid >> 2) * 64;   // 4 warps over 256 cols

    // ---- B tile: convert W1 -> fp16 once per CTA (256 cols x 32 float4) ----
#pragma unroll
    for (int u = tid; u < 8192; u += 512) {
        int c = u >> 5, q = u & 31;
        const float* wp = W1 + (size_t)(c & 127) * 256 + ((c >> 7) << 7) + q * 4;
        float4 v = *(const float4*)wp;
        __half2 h01(__float2half_rn(v.x), __float2half_rn(v.y));
        __half2 h23(__float2half_rn(v.z), __float2half_rn(v.w));
        *(uint2*)(smc + S_B + c * ROWB + q * 8) =
            make_uint2(*(uint32_t*)&h01, *(uint32_t*)&h23);
    }

    const int tig = lane & 3;
    float b1x[8], b1y[8];
#pragma unroll
    for (int nt = 0; nt < 8; nt++) {
        int col = warp_n + nt * 8 + 2 * tig;
        b1x[nt] = (col < 128) ? __ldg(b1 + col)     : 0.f;
        b1y[nt] = (col < 128) ? __ldg(b1 + col + 1) : 0.f;
    }

    for (int tile = blockIdx.x; tile < n_tiles; tile += gridDim.x) {
        const int n0 = tile * 128;
        __syncthreads();   // prior ldmatrix reads done before overwriting A

        // ---- A tile: load h, convert fp16 (8 float4/thread) ----
#pragma unroll
        for (int u = tid; u < 4096; u += 512) {
            int r = u >> 5, q = u & 31;
            int n = n0 + r;
            float4 v = make_float4(0.f, 0.f, 0.f, 0.f);
            if (n < n_nodes)
                v = *(const float4*)(h + (size_t)n * HF + q * 4);
            __half2 h01(__float2half_rn(v.x), __float2half_rn(v.y));
            __half2 h23(__float2half_rn(v.z), __float2half_rn(v.w));
            *(uint2*)(smc + S_A + r * ROWB + q * 8) =
                make_uint2(*(uint32_t*)&h01, *(uint32_t*)&h23);
        }
        __syncthreads();

        float acc[2][8][4];
#pragma unroll
        for (int mt = 0; mt < 2; mt++)
#pragma unroll
            for (int nt = 0; nt < 8; nt++)
#pragma unroll
                for (int i = 0; i < 4; i++) acc[mt][nt][i] = 0.f;

        // ---- MMA sweep: 8 k-steps of 16, single pass ----
#pragma unroll
        for (int ks = 0; ks < 8; ks++) {
            uint32_t ah[2][4];
#pragma unroll
            for (int mt = 0; mt < 2; mt++) {
                int row = warp_m + mt * 16 + (lane & 15);
                uint32_t addr = sb + S_A + row * ROWB + ks * 32 + ((lane >> 4) & 1) * 16;
                ldsm4(ah[mt], addr);
            }
#pragma unroll
            for (int np = 0; np < 4; np++) {
                int r = warp_n + np * 16 + (lane & 7) + ((lane >> 4) & 1) * 8;
                uint32_t addr = sb + S_B + r * ROWB + ks * 32 + ((lane >> 3) & 1) * 16;
                uint32_t bh[4];
                ldsm4(bh, addr);
#pragma unroll
                for (int mt = 0; mt < 2; mt++) {
                    mma_f16(acc[mt][2 * np],     ah[mt], bh);
                    mma_f16(acc[mt][2 * np + 1], ah[mt], bh + 2);
                }
            }
        }

        // ---- epilogue: cols <128 -> U (+b1), >=128 -> V; fp16 stores ----
        const int g = lane >> 2;
#pragma unroll
        for (int nt = 0; nt < 8; nt++) {
            int col = warp_n + nt * 8 + 2 * tig;
            const bool isU = (col < 128);
            __half* __restrict__ dest = isU ? g_U : g_V;
            int cc = isU ? col : (col - 128);
#pragma unroll
            for (int mt = 0; mt < 2; mt++) {
                int r0 = n0 + warp_m + mt * 16 + g;
                if (r0 < n_nodes)
                    *(__half2*)(dest + (size_t)r0 * HF + cc) =
                        __floats2half2_rn(acc[mt][nt][0] + b1x[nt],
                                          acc[mt][nt][1] + b1y[nt]);
                int r1 = r0 + 8;
                if (r1 < n_nodes)
                    *(__half2*)(dest + (size_t)r1 * HF + cc) =
                        __floats2half2_rn(acc[mt][nt][2] + b1x[nt],
                                          acc[mt][nt][3] + b1y[nt]);
            }
        }
    }
}

// ---------------------------------------------------------------------------
// Kernel 2: per-edge  score = W2 . relu(U'[src] + V[dst]) + b2   (b1 in U')
// 16 lanes/edge; 4 edges in flight per warp iteration (2x unroll) to cover
// gather latency. fp16 add/relu, fp32 dot.
// ---------------------------------------------------------------------------
__global__ __launch_bounds__(256) void edge_score_kernel(
    const void* __restrict__ src_raw,
    const void* __restrict__ dst_raw,
    const float* __restrict__ W2,
    const float* __restrict__ b2,
    float* __restrict__ out,
    int n_edges,
    int n_nodes)
{
    __shared__ int s_is64;
    if (threadIdx.x == 0) {
        const unsigned int* p = (const unsigned int*)src_raw;
        int slots = n_edges >> 1; if (slots > 64) slots = 64;
        unsigned int acc = 0;
        for (int i = 0; i < slots; i++) acc |= p[2 * i + 1];
        s_is64 = (acc == 0u) ? 1 : 0;
    }
    __syncthreads();
    const int is64 = s_is64;

    const int lane = threadIdx.x & 31;
    const int q    = lane >> 4;               // edge slot (0..1)
    const int t    = lane & 15;               // sub-lane within edge (0..15)
    const int warp   = (blockIdx.x * blockDim.x + threadIdx.x) >> 5;
    const int nwarps = (gridDim.x * blockDim.x) >> 5;

    float w2r[8];
    {
        float4 wa = ((const float4*)W2)[2 * t];
        float4 wb = ((const float4*)W2)[2 * t + 1];
        w2r[0] = wa.x; w2r[1] = wa.y; w2r[2] = wa.z; w2r[3] = wa.w;
        w2r[4] = wb.x; w2r[5] = wb.y; w2r[6] = wb.z; w2r[7] = wb.w;
    }
    const float b2v = __ldg(b2);
    const __half2 zero2 = __half2half2(__float2half(0.f));

    const int*       src32 = (const int*)src_raw;
    const int*       dst32 = (const int*)dst_raw;
    const long long* src64 = (const long long*)src_raw;
    const long long* dst64 = (const long long*)dst_raw;

    const int n_iter = (n_edges + 3) >> 2;    // 4 edges per warp iteration
    for (int it = warp; it < n_iter; it += nwarps) {
        const int e0 = it * 4 + q;            // this lane-group's 2 edges
        const int e1 = e0 + 2;
        const bool live0 = (e0 < n_edges);
        const bool live1 = (e1 < n_edges);

        int s0 = 0, d0 = 0, s1 = 0, d1 = 0;
        if (is64) {
            if (live0) { s0 = (int)__ldg(src64 + e0); d0 = (int)__ldg(dst64 + e0); }
            if (live1) { s1 = (int)__ldg(src64 + e1); d1 = (int)__ldg(dst64 + e1); }
        } else {
            if (live0) { s0 = __ldg(src32 + e0); d0 = __ldg(dst32 + e0); }
            if (live1) { s1 = __ldg(src32 + e1); d1 = __ldg(dst32 + e1); }
        }
        unsigned int su0 = ((unsigned int)s0 < (unsigned int)n_nodes) ? (unsigned int)s0 : 0u;
        unsigned int du0 = ((unsigned int)d0 < (unsigned int)n_nodes) ? (unsigned int)d0 : 0u;
        unsigned int su1 = ((unsigned int)s1 < (unsigned int)n_nodes) ? (unsigned int)s1 : 0u;
        unsigned int du1 = ((unsigned int)d1 < (unsigned int)n_nodes) ? (unsigned int)d1 : 0u;

        // 4 independent gathers in flight
        uint4 ua0 = ((const uint4*)(g_U + (size_t)su0 * HF))[t];
        uint4 va0 = ((const uint4*)(g_V + (size_t)du0 * HF))[t];
        uint4 ua1 = ((const uint4*)(g_U + (size_t)su1 * HF))[t];
        uint4 va1 = ((const uint4*)(g_V + (size_t)du1 * HF))[t];

        float acc0 = 0.f, acc1 = 0.f;
        {
            const __half2* up = (const __half2*)&ua0;
            const __half2* vp = (const __half2*)&va0;
#pragma unroll
            for (int i = 0; i < 4; i++) {
                __half2 z = __hmax2(__hadd2(up[i], vp[i]), zero2);
                float2 zf = __half22float2(z);
                acc0 = fmaf(zf.x, w2r[2 * i + 0], acc0);
                acc0 = fmaf(zf.y, w2r[2 * i + 1], acc0);
            }
        }
        {
            const __half2* up = (const __half2*)&ua1;
            const __half2* vp = (const __half2*)&va1;
#pragma unroll
            for (int i = 0; i < 4; i++) {
                __half2 z = __hmax2(__hadd2(up[i], vp[i]), zero2);
                float2 zf = __half22float2(z);
                acc1 = fmaf(zf.x, w2r[2 * i + 0], acc1);
                acc1 = fmaf(zf.y, w2r[2 * i + 1], acc1);
            }
        }
#pragma unroll
        for (int o = 1; o <= 8; o <<= 1) {
            acc0 += __shfl_xor_sync(0xffffffffu, acc0, o);
            acc1 += __shfl_xor_sync(0xffffffffu, acc1, o);
        }

        if (t == 0) {
            if (live0) out[e0] = acc0 + b2v;
            if (live1) out[e1] = acc1 + b2v;
        }
    }
}

// ---------------------------------------------------------------------------
// Launch
// ---------------------------------------------------------------------------
extern "C" void kernel_launch(void* const* d_in, const int* in_sizes, int n_in,
                              void* d_out, int out_size)
{
    const float* h   = (const float*)d_in[0];
    const void*  src = d_in[1];
    const void*  dst = d_in[2];
    const float* W1  = (const float*)d_in[3];
    const float* b1  = (const float*)d_in[4];
    const float* W2  = (const float*)d_in[5];
    const float* b2  = (const float*)d_in[6];
    float* out = (float*)d_out;

    const int n_nodes = in_sizes[0] / HF;
    const int n_edges = in_sizes[1];
    const int n_tiles = (n_nodes + 127) / 128;
    const int grid    = (n_tiles < 148) ? n_tiles : 148;

    cudaFuncSetAttribute(node_gemm_mma,
                         cudaFuncAttributeMaxDynamicSharedMemorySize, GEMM_SMEM);

    node_gemm_mma<<<grid, 512, GEMM_SMEM>>>(h, W1, b1, n_nodes, n_tiles);
    edge_score_kernel<<<1184, 256>>>(src, dst, W2, b2, out, n_edges, n_nodes);
}